// round 11
// baseline (speedup 1.0000x reference)
#include <cuda_runtime.h>
#include <cuda_bf16.h>
#include <math.h>
#include <stdint.h>

// ---------------- problem constants ----------------
#define BATCH 16
#define HH 112
#define WW 112
#define SS 7
#define DD 3
#define HEADS 6
#define DIM 192
#define HIDDEN 768
#define NWIN 49
#define WIN_PER_IMG 256
#define BW (BATCH * WIN_PER_IMG)   // 4096
#define TOKENS (BW * NWIN)         // 200704
#define HEADDIM 32
#define LPIX (HH * WW)
#define BCOL 56                    // padded bias row stride

typedef __nv_bfloat16 bf16;

// ---------------- scratch ----------------
__device__ bf16  g_win[(size_t)TOKENS * DIM];
__device__ bf16  g_q[(size_t)TOKENS * DIM];
__device__ bf16  g_k[(size_t)TOKENS * DIM];
__device__ bf16  g_v[(size_t)TOKENS * DIM];
__device__ bf16  g_att[(size_t)TOKENS * DIM];
__device__ float g_x1[(size_t)TOKENS * DIM];
__device__ bf16  g_h[(size_t)TOKENS * HIDDEN];
__device__ bf16  g_wqkv[3 * DIM * DIM];
__device__ bf16  g_wproj[DIM * DIM];
__device__ bf16  g_wfc1[HIDDEN * DIM];
__device__ bf16  g_wfc2[DIM * HIDDEN];
__device__ float g_bias[4 * HEADS * NWIN * BCOL];   // rpe+mask bias tables

// ---------------- ptx helpers ----------------
__device__ __forceinline__ uint32_t smem_u32(const void* p) {
    return (uint32_t)__cvta_generic_to_shared(p);
}
__device__ __forceinline__ void cp_async16(uint32_t s, const void* g) {
    asm volatile("cp.async.cg.shared.global [%0], [%1], 16;" :: "r"(s), "l"(g));
}
__device__ __forceinline__ void cp_commit() {
    asm volatile("cp.async.commit_group;");
}
template <int N>
__device__ __forceinline__ void cp_wait() {
    asm volatile("cp.async.wait_group %0;" :: "n"(N));
}
__device__ __forceinline__ void ldsm4(uint32_t& r0, uint32_t& r1, uint32_t& r2,
                                      uint32_t& r3, uint32_t addr) {
    asm volatile("ldmatrix.sync.aligned.m8n8.x4.shared.b16 {%0,%1,%2,%3}, [%4];"
                 : "=r"(r0), "=r"(r1), "=r"(r2), "=r"(r3) : "r"(addr));
}
__device__ __forceinline__ void ldsm4t(uint32_t& r0, uint32_t& r1, uint32_t& r2,
                                       uint32_t& r3, uint32_t addr) {
    asm volatile("ldmatrix.sync.aligned.m8n8.x4.trans.shared.b16 {%0,%1,%2,%3}, [%4];"
                 : "=r"(r0), "=r"(r1), "=r"(r2), "=r"(r3) : "r"(addr));
}
__device__ __forceinline__ void mma_bf16(float* d, const uint32_t* a, const uint32_t* b) {
    asm volatile(
        "mma.sync.aligned.m16n8k16.row.col.f32.bf16.bf16.f32 "
        "{%0,%1,%2,%3}, {%4,%5,%6,%7}, {%8,%9}, {%0,%1,%2,%3};"
        : "+f"(d[0]), "+f"(d[1]), "+f"(d[2]), "+f"(d[3])
        : "r"(a[0]), "r"(a[1]), "r"(a[2]), "r"(a[3]), "r"(b[0]), "r"(b[1]));
}
__device__ __forceinline__ uint32_t packbf(float a, float b) {
    __nv_bfloat162 t = __floats2bfloat162_rn(a, b);
    return *(uint32_t*)&t;
}

// ---------------- weight fp32 -> bf16 convert (all weights, 1 launch) ------
#define N4_QKV (3 * DIM * DIM / 4)
#define N4_PROJ (DIM * DIM / 4)
#define N4_FC1 (HIDDEN * DIM / 4)
#define N4_FC2 (DIM * HIDDEN / 4)
#define N4_ALL (N4_QKV + N4_PROJ + N4_FC1 + N4_FC2)
__global__ void cvt_all(const float4* s0, const float4* s1, const float4* s2,
                        const float4* s3, __nv_bfloat162* d0, __nv_bfloat162* d1,
                        __nv_bfloat162* d2, __nv_bfloat162* d3) {
    int i = blockIdx.x * 256 + threadIdx.x;
    const float4* s; __nv_bfloat162* d; int j = i;
    if (j < N4_QKV) { s = s0; d = d0; }
    else if ((j -= N4_QKV) < N4_PROJ) { s = s1; d = d1; }
    else if ((j -= N4_PROJ) < N4_FC1) { s = s2; d = d2; }
    else if ((j -= N4_FC1) < N4_FC2) { s = s3; d = d3; }
    else return;
    float4 v = s[j];
    d[2 * j]     = __floats2bfloat162_rn(v.x, v.y);
    d[2 * j + 1] = __floats2bfloat162_rn(v.z, v.w);
}

// ---------------- RPE+mask bias tables: 4 window types x 6 heads ----------
__global__ void build_bias(const float* __restrict__ rpe, float* __restrict__ bias) {
    int bt = blockIdx.x;                  // 0..23
    int type = bt / HEADS, h = bt - type * HEADS;
    int rbig = type >> 1, cbig = type & 1;
    const int LT[9] = {0, 5, 4, 7, 8, 6, 2, 3, 1};
    for (int idx = threadIdx.x; idx < NWIN * BCOL; idx += 256) {
        int row = idx / BCOL, col = idx - row * BCOL;
        float v;
        if (col >= NWIN) {
            v = -1e9f;
        } else {
            int ri = row / SS, rj = row - ri * SS;
            int ci = col / SS, cj = col - ci * SS;
            v = rpe[((ri - ci + 6) * 13 + (rj - cj + 6)) * HEADS + h];
            int rb_r = rbig ? (ri < (SS - DD) ? 1 : 2) : 0;
            int cb_r = cbig ? (rj < (SS - DD) ? 1 : 2) : 0;
            int rb_c = rbig ? (ci < (SS - DD) ? 1 : 2) : 0;
            int cb_c = cbig ? (cj < (SS - DD) ? 1 : 2) : 0;
            if (LT[rb_r * 3 + cb_r] != LT[rb_c * 3 + cb_c]) v -= 100.0f;
        }
        bias[(size_t)bt * NWIN * BCOL + idx] = v;
    }
}

// ---------------- LayerNorm (one warp per token), bf16 out ----------------
template <bool GATHER>
__global__ void ln_kernel(const float* __restrict__ x,
                          const float* __restrict__ gamma,
                          const float* __restrict__ beta,
                          bf16* __restrict__ out) {
    int warp = (blockIdx.x * blockDim.x + threadIdx.x) >> 5;
    int lane = threadIdx.x & 31;
    if (warp >= TOKENS) return;

    const float* src;
    if (GATHER) {
        int w = warp / NWIN, n = warp - w * NWIN;
        int b = w >> 8, ws = w & 255;
        int wh = ws >> 4, wc = ws & 15;
        int ii = n / SS, jj = n - ii * SS;
        int r = wh * SS + ii + DD; if (r >= HH) r -= HH;
        int c = wc * SS + jj + DD; if (c >= WW) c -= WW;
        src = x + ((size_t)b * LPIX + r * WW + c) * DIM;
    } else {
        src = x + (size_t)warp * DIM;
    }

    float v[6];
    float s = 0.f, s2 = 0.f;
#pragma unroll
    for (int k = 0; k < 6; k++) {
        v[k] = src[lane + 32 * k];
        s += v[k];
        s2 += v[k] * v[k];
    }
#pragma unroll
    for (int o = 16; o > 0; o >>= 1) {
        s  += __shfl_xor_sync(0xffffffffu, s, o);
        s2 += __shfl_xor_sync(0xffffffffu, s2, o);
    }
    float mu = s * (1.0f / DIM);
    float var = s2 * (1.0f / DIM) - mu * mu;
    float rstd = rsqrtf(var + 1e-5f);
    bf16* dst = out + (size_t)warp * DIM;
#pragma unroll
    for (int k = 0; k < 6; k++) {
        int cc = lane + 32 * k;
        dst[cc] = __float2bfloat16_rn((v[k] - mu) * rstd * gamma[cc] + beta[cc]);
    }
}

// ---------------- bf16 tensor-core GEMM (BN=64, 256 thr, 3 CTA/SM) --------
// Block 128x64x64, 8 warps (4m x 2n), warp tile 32x32.
// 3 stages, depth-2 prefetch, ONE __syncthreads per k-chunk.
#define BM 128
#define BN 64
#define A_STAGE 16384
#define B_STAGE 8192
#define STAGE_BYTES (A_STAGE + B_STAGE)       // 24576
#define GEMM_SMEM (3 * STAGE_BYTES)           // 73728

template <int EPI>
__global__ void __launch_bounds__(256, 3)
gemm_bf16(const bf16* __restrict__ A, const bf16* __restrict__ W,
          const float* __restrict__ bias,
          void* __restrict__ O0, void* __restrict__ O1, void* __restrict__ O2,
          const float* __restrict__ RES, int M, int N, int K) {
    extern __shared__ char sm[];
    const int t = threadIdx.x;
    const int wid = t >> 5, lane = t & 31;
    const int warp_m = wid & 3, warp_n = wid >> 2;
    const int m0 = blockIdx.y * BM;
    const int n0 = blockIdx.x * BN;
    const uint32_t sbase = smem_u32(sm);
    const int NT = K >> 6;

    const int lr = lane & 7, g2 = lane >> 3;

    float acc[2][4][4] = {};

    auto issue = [&](int kt) {
        int s = kt % 3;
        const char* Ab = (const char*)(A + (size_t)m0 * K + kt * 64);
        uint32_t as = sbase + s * STAGE_BYTES;
#pragma unroll
        for (int i = 0; i < 4; i++) {
            int id = i * 256 + t;
            int row = id >> 3, c = id & 7;
            cp_async16(as + row * 128 + ((c * 16) ^ ((row & 7) << 4)),
                       Ab + (size_t)row * K * 2 + c * 16);
        }
        const char* Bb = (const char*)(W + (size_t)n0 * K + kt * 64);
        uint32_t bs = as + A_STAGE;
#pragma unroll
        for (int i = 0; i < 2; i++) {
            int id = i * 256 + t;
            int row = id >> 3, c = id & 7;
            cp_async16(bs + row * 128 + ((c * 16) ^ ((row & 7) << 4)),
                       Bb + (size_t)row * K * 2 + c * 16);
        }
    };

    issue(0); cp_commit();
    if (NT > 1) issue(1);
    cp_commit();

    for (int kt = 0; kt < NT; kt++) {
        cp_wait<1>();
        __syncthreads();           // all warps done with stage (kt+2)%3's prior use
        if (kt + 2 < NT) issue(kt + 2);
        cp_commit();

        int s = kt % 3;
        uint32_t as = sbase + s * STAGE_BYTES;
        uint32_t bs = as + A_STAGE;
#pragma unroll
        for (int ks = 0; ks < 4; ks++) {
            uint32_t a[2][4], b[4][2];
            const int kb = ks * 32;
#pragma unroll
            for (int mf = 0; mf < 2; mf++) {
                int row = warp_m * 32 + mf * 16 + lr + (g2 & 1) * 8;
                int col = kb + (g2 >> 1) * 16;
                ldsm4(a[mf][0], a[mf][1], a[mf][2], a[mf][3],
                      as + row * 128 + (col ^ ((row & 7) << 4)));
            }
#pragma unroll
            for (int p = 0; p < 2; p++) {
                int row = warp_n * 32 + p * 16 + lr + (g2 >> 1) * 8;
                int col = kb + (g2 & 1) * 16;
                uint32_t r0, r1, r2, r3;
                ldsm4(r0, r1, r2, r3, bs + row * 128 + (col ^ ((row & 7) << 4)));
                b[p * 2][0] = r0;     b[p * 2][1] = r1;
                b[p * 2 + 1][0] = r2; b[p * 2 + 1][1] = r3;
            }
#pragma unroll
            for (int mf = 0; mf < 2; mf++)
#pragma unroll
                for (int nf = 0; nf < 4; nf++)
                    mma_bf16(acc[mf][nf], a[mf], b[nf]);
        }
    }

    const int gq = lane >> 2, qq = lane & 3;
#pragma unroll
    for (int mf = 0; mf < 2; mf++) {
#pragma unroll
        for (int nf = 0; nf < 4; nf++) {
#pragma unroll
            for (int half = 0; half < 2; half++) {
                int r = m0 + warp_m * 32 + mf * 16 + gq + half * 8;
                int c = n0 + warp_n * 32 + nf * 8 + 2 * qq;
                float v0 = acc[mf][nf][2 * half + 0] + bias[c];
                float v1 = acc[mf][nf][2 * half + 1] + bias[c + 1];
                if (EPI == 0) {
                    int which = c / DIM;
                    int c2 = c - which * DIM;
                    int hd = c2 >> 5, dd = c2 & 31;
                    int w = r / NWIN, n = r - w * NWIN;
                    size_t off = ((size_t)(w * HEADS + hd) * NWIN + n) * HEADDIM + dd;
                    bf16* dst = (which == 0) ? (bf16*)O0 : (which == 1) ? (bf16*)O1 : (bf16*)O2;
                    if (which == 0) { v0 *= 0.17677669529663687f; v1 *= 0.17677669529663687f; }
                    *(__nv_bfloat162*)(dst + off) = __floats2bfloat162_rn(v0, v1);
                } else if (EPI == 1) {
                    int w = r / NWIN, n = r - w * NWIN;
                    int b = w >> 8, ws = w & 255;
                    int wh = ws >> 4, wc = ws & 15;
                    int ii = n / SS, jj = n - ii * SS;
                    int rr = wh * SS + ii + DD; if (rr >= HH) rr -= HH;
                    int cc = wc * SS + jj + DD; if (cc >= WW) cc -= WW;
                    size_t dst = ((size_t)b * LPIX + rr * WW + cc) * DIM + c;
                    float* o = (float*)O0;
                    o[dst] = v0 + RES[dst];
                    o[dst + 1] = v1 + RES[dst + 1];
                } else if (EPI == 2) {
                    size_t idx = (size_t)r * N + c;
                    float g0 = 0.5f * v0 * (1.0f + erff(v0 * 0.70710678118654752f));
                    float g1 = 0.5f * v1 * (1.0f + erff(v1 * 0.70710678118654752f));
                    *(__nv_bfloat162*)((bf16*)O0 + idx) = __floats2bfloat162_rn(g0, g1);
                } else {
                    size_t idx = (size_t)r * N + c;
                    float* o = (float*)O0;
                    o[idx] = v0 + RES[idx];
                    o[idx + 1] = v1 + RES[idx + 1];
                }
            }
        }
    }
}

// ---------------- attention via mma: one block per (window, head) ----------
#define AST 40
__global__ void __launch_bounds__(128)
attn_kernel(const bf16* __restrict__ q, const bf16* __restrict__ k,
            const bf16* __restrict__ v, const float* __restrict__ bias,
            bf16* __restrict__ out) {
    int bh = blockIdx.x;
    int w = bh / HEADS, h = bh - w * HEADS;

    __shared__ bf16 qs[64 * AST];
    __shared__ bf16 ks[64 * AST];
    __shared__ bf16 vs[64 * AST];

    const int t = threadIdx.x;
    const int wm = t >> 5, lane = t & 31;

    {
        const uint4* qg = (const uint4*)(q + (size_t)bh * NWIN * HEADDIM);
        const uint4* kg = (const uint4*)(k + (size_t)bh * NWIN * HEADDIM);
        const uint4* vg = (const uint4*)(v + (size_t)bh * NWIN * HEADDIM);
        const uint4 zz = make_uint4(0, 0, 0, 0);
#pragma unroll
        for (int it = 0; it < 2; it++) {
            int task = it * 128 + t;
            int row = task >> 2, seg = task & 3;
            bool ok = row < NWIN;
            *(uint4*)&qs[row * AST + seg * 8] = ok ? qg[row * 4 + seg] : zz;
            *(uint4*)&ks[row * AST + seg * 8] = ok ? kg[row * 4 + seg] : zz;
            *(uint4*)&vs[row * AST + seg * 8] = ok ? vg[row * 4 + seg] : zz;
        }
    }
    __syncthreads();

    const uint32_t sq = smem_u32(qs), sk = smem_u32(ks), sv = smem_u32(vs);
    const int sub = lane >> 3, l7 = lane & 7;

    float c[7][4] = {};
#pragma unroll
    for (int kc = 0; kc < 2; kc++) {
        uint32_t a[4];
        {
            int row = wm * 16 + (sub & 1) * 8 + l7;
            int col = kc * 32 + (sub >> 1) * 16;
            ldsm4(a[0], a[1], a[2], a[3], sq + row * (AST * 2) + col);
        }
#pragma unroll
        for (int p = 0; p < 4; p++) {
            int n = p * 16 + (sub >> 1) * 8 + l7;
            int col = kc * 32 + (sub & 1) * 16;
            uint32_t r0, r1, r2, r3;
            ldsm4(r0, r1, r2, r3, sk + n * (AST * 2) + col);
            uint32_t b0[2] = {r0, r1};
            mma_bf16(c[2 * p], a, b0);
            if (p < 3) {
                uint32_t b1[2] = {r2, r3};
                mma_bf16(c[2 * p + 1], a, b1);
            }
        }
    }

    const int g = lane >> 2, qd = lane & 3;
    const int row0 = wm * 16 + g, row1 = row0 + 8;
    const int rr0 = row0 < NWIN ? row0 : 0;
    const int rr1 = row1 < NWIN ? row1 : 0;
    {
        int ws = w & 255;
        int type = (((ws >> 4) == 15) << 1) | ((ws & 15) == 15);
        const float* btab = bias + (size_t)(type * HEADS + h) * NWIN * BCOL;
        const float* bt0 = btab + rr0 * BCOL + 2 * qd;
        const float* bt1 = btab + rr1 * BCOL + 2 * qd;
#pragma unroll
        for (int tt = 0; tt < 7; tt++) {
            float2 b0 = *(const float2*)&bt0[tt * 8];
            float2 b1 = *(const float2*)&bt1[tt * 8];
            c[tt][0] += b0.x; c[tt][1] += b0.y;
            c[tt][2] += b1.x; c[tt][3] += b1.y;
        }
    }

    {
        float mx = -1e30f;
#pragma unroll
        for (int tt = 0; tt < 7; tt++) mx = fmaxf(mx, fmaxf(c[tt][0], c[tt][1]));
        mx = fmaxf(mx, __shfl_xor_sync(0xffffffffu, mx, 1));
        mx = fmaxf(mx, __shfl_xor_sync(0xffffffffu, mx, 2));
        float sum = 0.f;
#pragma unroll
        for (int tt = 0; tt < 7; tt++) {
            c[tt][0] = __expf(c[tt][0] - mx); sum += c[tt][0];
            c[tt][1] = __expf(c[tt][1] - mx); sum += c[tt][1];
        }
        sum += __shfl_xor_sync(0xffffffffu, sum, 1);
        sum += __shfl_xor_sync(0xffffffffu, sum, 2);
        float inv = 1.0f / sum;
#pragma unroll
        for (int tt = 0; tt < 7; tt++) { c[tt][0] *= inv; c[tt][1] *= inv; }
    }
    {
        float mx = -1e30f;
#pragma unroll
        for (int tt = 0; tt < 7; tt++) mx = fmaxf(mx, fmaxf(c[tt][2], c[tt][3]));
        mx = fmaxf(mx, __shfl_xor_sync(0xffffffffu, mx, 1));
        mx = fmaxf(mx, __shfl_xor_sync(0xffffffffu, mx, 2));
        float sum = 0.f;
#pragma unroll
        for (int tt = 0; tt < 7; tt++) {
            c[tt][2] = __expf(c[tt][2] - mx); sum += c[tt][2];
            c[tt][3] = __expf(c[tt][3] - mx); sum += c[tt][3];
        }
        sum += __shfl_xor_sync(0xffffffffu, sum, 1);
        sum += __shfl_xor_sync(0xffffffffu, sum, 2);
        float inv = 1.0f / sum;
#pragma unroll
        for (int tt = 0; tt < 7; tt++) { c[tt][2] *= inv; c[tt][3] *= inv; }
    }

    float o[4][4] = {};
#pragma unroll
    for (int kc = 0; kc < 4; kc++) {
        uint32_t a[4];
        a[0] = packbf(c[2 * kc][0], c[2 * kc][1]);
        a[1] = packbf(c[2 * kc][2], c[2 * kc][3]);
        if (2 * kc + 1 < 7) {
            a[2] = packbf(c[2 * kc + 1][0], c[2 * kc + 1][1]);
            a[3] = packbf(c[2 * kc + 1][2], c[2 * kc + 1][3]);
        } else {
            a[2] = 0; a[3] = 0;
        }
#pragma unroll
        for (int p = 0; p < 2; p++) {
            int row = kc * 16 + (sub & 1) * 8 + l7;
            int col = p * 32 + (sub >> 1) * 16;
            uint32_t r0, r1, r2, r3;
            ldsm4t(r0, r1, r2, r3, sv + row * (AST * 2) + col);
            uint32_t b0[2] = {r0, r1}, b1[2] = {r2, r3};
            mma_bf16(o[2 * p], a, b0);
            mma_bf16(o[2 * p + 1], a, b1);
        }
    }

    bf16* ob = out + (size_t)w * NWIN * DIM + h * HEADDIM;
    if (row0 < NWIN) {
#pragma unroll
        for (int nt = 0; nt < 4; nt++) {
            __nv_bfloat162 pv = __floats2bfloat162_rn(o[nt][0], o[nt][1]);
            *(__nv_bfloat162*)&ob[(size_t)row0 * DIM + nt * 8 + 2 * qd] = pv;
        }
    }
    if (row1 < NWIN) {
#pragma unroll
        for (int nt = 0; nt < 4; nt++) {
            __nv_bfloat162 pv = __floats2bfloat162_rn(o[nt][2], o[nt][3]);
            *(__nv_bfloat162*)&ob[(size_t)row1 * DIM + nt * 8 + 2 * qd] = pv;
        }
    }
}

// ---------------- launcher ----------------
extern "C" void kernel_launch(void* const* d_in, const int* in_sizes, int n_in,
                              void* d_out, int out_size) {
    const float* x      = (const float*)d_in[0];
    const float* w_qkv  = (const float*)d_in[1];
    const float* b_qkv  = (const float*)d_in[2];
    const float* w_proj = (const float*)d_in[3];
    const float* b_proj = (const float*)d_in[4];
    const float* rpe    = (const float*)d_in[5];
    const float* gamma1 = (const float*)d_in[6];
    const float* beta1  = (const float*)d_in[7];
    const float* gamma2 = (const float*)d_in[8];
    const float* beta2  = (const float*)d_in[9];
    const float* w_fc1  = (const float*)d_in[10];
    const float* b_fc1  = (const float*)d_in[11];
    const float* w_fc2  = (const float*)d_in[12];
    const float* b_fc2  = (const float*)d_in[13];
    float* out = (float*)d_out;

    bf16 *win, *q, *k, *v, *att, *hbuf, *wqkv, *wproj, *wfc1, *wfc2;
    float *x1, *bias;
    cudaGetSymbolAddress((void**)&win,   g_win);
    cudaGetSymbolAddress((void**)&q,     g_q);
    cudaGetSymbolAddress((void**)&k,     g_k);
    cudaGetSymbolAddress((void**)&v,     g_v);
    cudaGetSymbolAddress((void**)&att,   g_att);
    cudaGetSymbolAddress((void**)&x1,    g_x1);
    cudaGetSymbolAddress((void**)&hbuf,  g_h);
    cudaGetSymbolAddress((void**)&wqkv,  g_wqkv);
    cudaGetSymbolAddress((void**)&wproj, g_wproj);
    cudaGetSymbolAddress((void**)&wfc1,  g_wfc1);
    cudaGetSymbolAddress((void**)&wfc2,  g_wfc2);
    cudaGetSymbolAddress((void**)&bias,  g_bias);

    cudaFuncSetAttribute(gemm_bf16<0>, cudaFuncAttributeMaxDynamicSharedMemorySize, GEMM_SMEM);
    cudaFuncSetAttribute(gemm_bf16<1>, cudaFuncAttributeMaxDynamicSharedMemorySize, GEMM_SMEM);
    cudaFuncSetAttribute(gemm_bf16<2>, cudaFuncAttributeMaxDynamicSharedMemorySize, GEMM_SMEM);
    cudaFuncSetAttribute(gemm_bf16<3>, cudaFuncAttributeMaxDynamicSharedMemorySize, GEMM_SMEM);

    // 0) weight conversions + bias table
    cvt_all<<<(N4_ALL + 255) / 256, 256>>>(
        (const float4*)w_qkv, (const float4*)w_proj, (const float4*)w_fc1,
        (const float4*)w_fc2, (__nv_bfloat162*)wqkv, (__nv_bfloat162*)wproj,
        (__nv_bfloat162*)wfc1, (__nv_bfloat162*)wfc2);
    build_bias<<<4 * HEADS, 256>>>(rpe, bias);

    const int LN_BLOCKS = TOKENS / 8;
    const int MT = TOKENS / BM;   // 1568

    // 1) LN1 + shift + window gather
    ln_kernel<true><<<LN_BLOCKS, 256>>>(x, gamma1, beta1, win);

    // 2) QKV GEMM (N=576 -> 9 column tiles)
    gemm_bf16<0><<<dim3(576 / BN, MT), 256, GEMM_SMEM>>>(
        win, wqkv, b_qkv, q, k, v, nullptr, TOKENS, 3 * DIM, DIM);

    // 3) windowed attention (mma + bias table)
    attn_kernel<<<BW * HEADS, 128>>>(q, k, v, bias, att);

    // 4) proj GEMM + unshift + residual -> x1 (fp32)
    gemm_bf16<1><<<dim3(DIM / BN, MT), 256, GEMM_SMEM>>>(
        att, wproj, b_proj, x1, nullptr, nullptr, x, TOKENS, DIM, DIM);

    // 5) LN2 -> bf16
    ln_kernel<false><<<LN_BLOCKS, 256>>>(x1, gamma2, beta2, win);

    // 6) fc1 GEMM + GELU (N=768) -> bf16
    gemm_bf16<2><<<dim3(HIDDEN / BN, MT), 256, GEMM_SMEM>>>(
        win, wfc1, b_fc1, hbuf, nullptr, nullptr, nullptr, TOKENS, HIDDEN, DIM);

    // 7) fc2 GEMM + residual(x1) -> fp32 d_out (K=768)
    gemm_bf16<3><<<dim3(DIM / BN, MT), 256, GEMM_SMEM>>>(
        hbuf, wfc2, b_fc2, out, nullptr, nullptr, x1, TOKENS, DIM, HIDDEN);
}

// round 14
// speedup vs baseline: 1.1841x; 1.1841x over previous
#include <cuda_runtime.h>
#include <cuda_bf16.h>
#include <math.h>
#include <stdint.h>

// ---------------- problem constants ----------------
#define BATCH 16
#define HH 112
#define WW 112
#define SS 7
#define DD 3
#define HEADS 6
#define DIM 192
#define HIDDEN 768
#define NWIN 49
#define WIN_PER_IMG 256
#define BW (BATCH * WIN_PER_IMG)   // 4096
#define TOKENS (BW * NWIN)         // 200704
#define HEADDIM 32
#define LPIX (HH * WW)
#define BCOL 56                    // padded bias row stride

typedef __nv_bfloat16 bf16;

// ---------------- scratch ----------------
__device__ bf16  g_win[(size_t)TOKENS * DIM];
__device__ bf16  g_q[(size_t)TOKENS * DIM];
__device__ bf16  g_k[(size_t)TOKENS * DIM];
__device__ bf16  g_v[(size_t)TOKENS * DIM];
__device__ bf16  g_att[(size_t)TOKENS * DIM];
__device__ float g_x1[(size_t)TOKENS * DIM];
__device__ bf16  g_h[(size_t)TOKENS * HIDDEN];
__device__ bf16  g_wqkv[3 * DIM * DIM];
__device__ bf16  g_wproj[DIM * DIM];
__device__ bf16  g_wfc1[HIDDEN * DIM];
__device__ bf16  g_wfc2[DIM * HIDDEN];
__device__ float g_bias[4 * HEADS * NWIN * BCOL];   // rpe+mask bias tables

// ---------------- ptx helpers ----------------
__device__ __forceinline__ uint32_t smem_u32(const void* p) {
    return (uint32_t)__cvta_generic_to_shared(p);
}
__device__ __forceinline__ void cp_async16(uint32_t s, const void* g) {
    asm volatile("cp.async.cg.shared.global [%0], [%1], 16;" :: "r"(s), "l"(g));
}
__device__ __forceinline__ void cp_commit() {
    asm volatile("cp.async.commit_group;");
}
template <int N>
__device__ __forceinline__ void cp_wait() {
    asm volatile("cp.async.wait_group %0;" :: "n"(N));
}
__device__ __forceinline__ void ldsm4(uint32_t& r0, uint32_t& r1, uint32_t& r2,
                                      uint32_t& r3, uint32_t addr) {
    asm volatile("ldmatrix.sync.aligned.m8n8.x4.shared.b16 {%0,%1,%2,%3}, [%4];"
                 : "=r"(r0), "=r"(r1), "=r"(r2), "=r"(r3) : "r"(addr));
}
__device__ __forceinline__ void ldsm4t(uint32_t& r0, uint32_t& r1, uint32_t& r2,
                                       uint32_t& r3, uint32_t addr) {
    asm volatile("ldmatrix.sync.aligned.m8n8.x4.trans.shared.b16 {%0,%1,%2,%3}, [%4];"
                 : "=r"(r0), "=r"(r1), "=r"(r2), "=r"(r3) : "r"(addr));
}
__device__ __forceinline__ void mma_bf16(float* d, const uint32_t* a, const uint32_t* b) {
    asm volatile(
        "mma.sync.aligned.m16n8k16.row.col.f32.bf16.bf16.f32 "
        "{%0,%1,%2,%3}, {%4,%5,%6,%7}, {%8,%9}, {%0,%1,%2,%3};"
        : "+f"(d[0]), "+f"(d[1]), "+f"(d[2]), "+f"(d[3])
        : "r"(a[0]), "r"(a[1]), "r"(a[2]), "r"(a[3]), "r"(b[0]), "r"(b[1]));
}
__device__ __forceinline__ uint32_t packbf(float a, float b) {
    __nv_bfloat162 t = __floats2bfloat162_rn(a, b);
    return *(uint32_t*)&t;
}

// ---------------- weight fp32 -> bf16 convert (all weights, 1 launch) ------
#define N4_QKV (3 * DIM * DIM / 4)
#define N4_PROJ (DIM * DIM / 4)
#define N4_FC1 (HIDDEN * DIM / 4)
#define N4_FC2 (DIM * HIDDEN / 4)
#define N4_ALL (N4_QKV + N4_PROJ + N4_FC1 + N4_FC2)
__global__ void cvt_all(const float4* s0, const float4* s1, const float4* s2,
                        const float4* s3, __nv_bfloat162* d0, __nv_bfloat162* d1,
                        __nv_bfloat162* d2, __nv_bfloat162* d3) {
    int i = blockIdx.x * 256 + threadIdx.x;
    const float4* s; __nv_bfloat162* d; int j = i;
    if (j < N4_QKV) { s = s0; d = d0; }
    else if ((j -= N4_QKV) < N4_PROJ) { s = s1; d = d1; }
    else if ((j -= N4_PROJ) < N4_FC1) { s = s2; d = d2; }
    else if ((j -= N4_FC1) < N4_FC2) { s = s3; d = d3; }
    else return;
    float4 v = s[j];
    d[2 * j]     = __floats2bfloat162_rn(v.x, v.y);
    d[2 * j + 1] = __floats2bfloat162_rn(v.z, v.w);
}

// ---------------- RPE+mask bias tables: 4 window types x 6 heads ----------
__global__ void build_bias(const float* __restrict__ rpe, float* __restrict__ bias) {
    int bt = blockIdx.x;                  // 0..23
    int type = bt / HEADS, h = bt - type * HEADS;
    int rbig = type >> 1, cbig = type & 1;
    const int LT[9] = {0, 5, 4, 7, 8, 6, 2, 3, 1};
    for (int idx = threadIdx.x; idx < NWIN * BCOL; idx += 256) {
        int row = idx / BCOL, col = idx - row * BCOL;
        float v;
        if (col >= NWIN) {
            v = -1e9f;
        } else {
            int ri = row / SS, rj = row - ri * SS;
            int ci = col / SS, cj = col - ci * SS;
            v = rpe[((ri - ci + 6) * 13 + (rj - cj + 6)) * HEADS + h];
            int rb_r = rbig ? (ri < (SS - DD) ? 1 : 2) : 0;
            int cb_r = cbig ? (rj < (SS - DD) ? 1 : 2) : 0;
            int rb_c = rbig ? (ci < (SS - DD) ? 1 : 2) : 0;
            int cb_c = cbig ? (cj < (SS - DD) ? 1 : 2) : 0;
            if (LT[rb_r * 3 + cb_r] != LT[rb_c * 3 + cb_c]) v -= 100.0f;
        }
        bias[(size_t)bt * NWIN * BCOL + idx] = v;
    }
}

// ---------------- LayerNorm (one warp per token), bf16 out ----------------
template <bool GATHER>
__global__ void ln_kernel(const float* __restrict__ x,
                          const float* __restrict__ gamma,
                          const float* __restrict__ beta,
                          bf16* __restrict__ out) {
    int warp = (blockIdx.x * blockDim.x + threadIdx.x) >> 5;
    int lane = threadIdx.x & 31;
    if (warp >= TOKENS) return;

    const float* src;
    if (GATHER) {
        int w = warp / NWIN, n = warp - w * NWIN;
        int b = w >> 8, ws = w & 255;
        int wh = ws >> 4, wc = ws & 15;
        int ii = n / SS, jj = n - ii * SS;
        int r = wh * SS + ii + DD; if (r >= HH) r -= HH;
        int c = wc * SS + jj + DD; if (c >= WW) c -= WW;
        src = x + ((size_t)b * LPIX + r * WW + c) * DIM;
    } else {
        src = x + (size_t)warp * DIM;
    }

    float v[6];
    float s = 0.f, s2 = 0.f;
#pragma unroll
    for (int k = 0; k < 6; k++) {
        v[k] = src[lane + 32 * k];
        s += v[k];
        s2 += v[k] * v[k];
    }
#pragma unroll
    for (int o = 16; o > 0; o >>= 1) {
        s  += __shfl_xor_sync(0xffffffffu, s, o);
        s2 += __shfl_xor_sync(0xffffffffu, s2, o);
    }
    float mu = s * (1.0f / DIM);
    float var = s2 * (1.0f / DIM) - mu * mu;
    float rstd = rsqrtf(var + 1e-5f);
    bf16* dst = out + (size_t)warp * DIM;
#pragma unroll
    for (int k = 0; k < 6; k++) {
        int cc = lane + 32 * k;
        dst[cc] = __float2bfloat16_rn((v[k] - mu) * rstd * gamma[cc] + beta[cc]);
    }
}

// ---------------- bf16 tensor-core GEMM (BN=96, 256 thr, 2 CTA/SM) --------
// Block 128x96x64, 8 warps (4m x 2n), warp tile 32x48.
// 3 stages, depth-2 prefetch, ONE __syncthreads per k-chunk.
#define BM 128
#define BN 96
#define A_STAGE 16384
#define B_STAGE 12288
#define STAGE_BYTES (A_STAGE + B_STAGE)       // 28672
#define GEMM_SMEM (3 * STAGE_BYTES)           // 86016

template <int EPI>
__global__ void __launch_bounds__(256, 2)
gemm_bf16(const bf16* __restrict__ A, const bf16* __restrict__ W,
          const float* __restrict__ bias,
          void* __restrict__ O0, void* __restrict__ O1, void* __restrict__ O2,
          const float* __restrict__ RES, int M, int N, int K) {
    extern __shared__ char sm[];
    const int t = threadIdx.x;
    const int wid = t >> 5, lane = t & 31;
    const int warp_m = wid & 3, warp_n = wid >> 2;
    const int m0 = blockIdx.y * BM;
    const int n0 = blockIdx.x * BN;
    const uint32_t sbase = smem_u32(sm);
    const int NT = K >> 6;

    const int lr = lane & 7, g2 = lane >> 3;

    float acc[2][6][4] = {};

    auto issue = [&](int kt) {
        int s = kt % 3;
        const char* Ab = (const char*)(A + (size_t)m0 * K + kt * 64);
        uint32_t as = sbase + s * STAGE_BYTES;
#pragma unroll
        for (int i = 0; i < 4; i++) {
            int id = i * 256 + t;
            int row = id >> 3, c = id & 7;
            cp_async16(as + row * 128 + ((c * 16) ^ ((row & 7) << 4)),
                       Ab + (size_t)row * K * 2 + c * 16);
        }
        const char* Bb = (const char*)(W + (size_t)n0 * K + kt * 64);
        uint32_t bs = as + A_STAGE;
#pragma unroll
        for (int i = 0; i < 3; i++) {
            int id = i * 256 + t;
            int row = id >> 3, c = id & 7;
            cp_async16(bs + row * 128 + ((c * 16) ^ ((row & 7) << 4)),
                       Bb + (size_t)row * K * 2 + c * 16);
        }
    };

    issue(0); cp_commit();
    if (NT > 1) issue(1);
    cp_commit();

    for (int kt = 0; kt < NT; kt++) {
        cp_wait<1>();
        __syncthreads();           // stage (kt+2)%3's prior contents consumed pre-barrier
        if (kt + 2 < NT) issue(kt + 2);
        cp_commit();

        int s = kt % 3;
        uint32_t as = sbase + s * STAGE_BYTES;
        uint32_t bs = as + A_STAGE;
#pragma unroll
        for (int ks = 0; ks < 4; ks++) {
            uint32_t a[2][4], b[6][2];
            const int kb = ks * 32;
#pragma unroll
            for (int mf = 0; mf < 2; mf++) {
                int row = warp_m * 32 + mf * 16 + lr + (g2 & 1) * 8;
                int col = kb + (g2 >> 1) * 16;
                ldsm4(a[mf][0], a[mf][1], a[mf][2], a[mf][3],
                      as + row * 128 + (col ^ ((row & 7) << 4)));
            }
#pragma unroll
            for (int p = 0; p < 3; p++) {
                int row = warp_n * 48 + p * 16 + lr + (g2 >> 1) * 8;
                int col = kb + (g2 & 1) * 16;
                uint32_t r0, r1, r2, r3;
                ldsm4(r0, r1, r2, r3, bs + row * 128 + (col ^ ((row & 7) << 4)));
                b[p * 2][0] = r0;     b[p * 2][1] = r1;
                b[p * 2 + 1][0] = r2; b[p * 2 + 1][1] = r3;
            }
#pragma unroll
            for (int mf = 0; mf < 2; mf++)
#pragma unroll
                for (int nf = 0; nf < 6; nf++)
                    mma_bf16(acc[mf][nf], a[mf], b[nf]);
        }
    }

    const int gq = lane >> 2, qq = lane & 3;
#pragma unroll
    for (int mf = 0; mf < 2; mf++) {
#pragma unroll
        for (int nf = 0; nf < 6; nf++) {
#pragma unroll
            for (int half = 0; half < 2; half++) {
                int r = m0 + warp_m * 32 + mf * 16 + gq + half * 8;
                int c = n0 + warp_n * 48 + nf * 8 + 2 * qq;
                float v0 = acc[mf][nf][2 * half + 0] + bias[c];
                float v1 = acc[mf][nf][2 * half + 1] + bias[c + 1];
                if (EPI == 0) {
                    int which = c / DIM;
                    int c2 = c - which * DIM;
                    int hd = c2 >> 5, dd = c2 & 31;
                    int w = r / NWIN, n = r - w * NWIN;
                    size_t off = ((size_t)(w * HEADS + hd) * NWIN + n) * HEADDIM + dd;
                    bf16* dst = (which == 0) ? (bf16*)O0 : (which == 1) ? (bf16*)O1 : (bf16*)O2;
                    if (which == 0) { v0 *= 0.17677669529663687f; v1 *= 0.17677669529663687f; }
                    *(__nv_bfloat162*)(dst + off) = __floats2bfloat162_rn(v0, v1);
                } else if (EPI == 1) {
                    int w = r / NWIN, n = r - w * NWIN;
                    int b = w >> 8, ws = w & 255;
                    int wh = ws >> 4, wc = ws & 15;
                    int ii = n / SS, jj = n - ii * SS;
                    int rr = wh * SS + ii + DD; if (rr >= HH) rr -= HH;
                    int cc = wc * SS + jj + DD; if (cc >= WW) cc -= WW;
                    size_t dst = ((size_t)b * LPIX + rr * WW + cc) * DIM + c;
                    float* o = (float*)O0;
                    o[dst] = v0 + RES[dst];
                    o[dst + 1] = v1 + RES[dst + 1];
                } else if (EPI == 2) {
                    size_t idx = (size_t)r * N + c;
                    float g0 = 0.5f * v0 * (1.0f + erff(v0 * 0.70710678118654752f));
                    float g1 = 0.5f * v1 * (1.0f + erff(v1 * 0.70710678118654752f));
                    *(__nv_bfloat162*)((bf16*)O0 + idx) = __floats2bfloat162_rn(g0, g1);
                } else {
                    size_t idx = (size_t)r * N + c;
                    float* o = (float*)O0;
                    o[idx] = v0 + RES[idx];
                    o[idx + 1] = v1 + RES[idx + 1];
                }
            }
        }
    }
}

// ---------------- attention via mma: one block per (window, head) ----------
#define AST 40
__global__ void __launch_bounds__(128)
attn_kernel(const bf16* __restrict__ q, const bf16* __restrict__ k,
            const bf16* __restrict__ v, const float* __restrict__ bias,
            bf16* __restrict__ out) {
    int bh = blockIdx.x;
    int w = bh / HEADS, h = bh - w * HEADS;

    __shared__ bf16 qs[64 * AST];
    __shared__ bf16 ks[64 * AST];
    __shared__ bf16 vs[64 * AST];

    const int t = threadIdx.x;
    const int wm = t >> 5, lane = t & 31;

    {
        const uint4* qg = (const uint4*)(q + (size_t)bh * NWIN * HEADDIM);
        const uint4* kg = (const uint4*)(k + (size_t)bh * NWIN * HEADDIM);
        const uint4* vg = (const uint4*)(v + (size_t)bh * NWIN * HEADDIM);
        const uint4 zz = make_uint4(0, 0, 0, 0);
#pragma unroll
        for (int it = 0; it < 2; it++) {
            int task = it * 128 + t;
            int row = task >> 2, seg = task & 3;
            bool ok = row < NWIN;
            *(uint4*)&qs[row * AST + seg * 8] = ok ? qg[row * 4 + seg] : zz;
            *(uint4*)&ks[row * AST + seg * 8] = ok ? kg[row * 4 + seg] : zz;
            *(uint4*)&vs[row * AST + seg * 8] = ok ? vg[row * 4 + seg] : zz;
        }
    }
    __syncthreads();

    const uint32_t sq = smem_u32(qs), sk = smem_u32(ks), sv = smem_u32(vs);
    const int sub = lane >> 3, l7 = lane & 7;

    float c[7][4] = {};
#pragma unroll
    for (int kc = 0; kc < 2; kc++) {
        uint32_t a[4];
        {
            int row = wm * 16 + (sub & 1) * 8 + l7;
            int col = kc * 32 + (sub >> 1) * 16;
            ldsm4(a[0], a[1], a[2], a[3], sq + row * (AST * 2) + col);
        }
#pragma unroll
        for (int p = 0; p < 4; p++) {
            int n = p * 16 + (sub >> 1) * 8 + l7;
            int col = kc * 32 + (sub & 1) * 16;
            uint32_t r0, r1, r2, r3;
            ldsm4(r0, r1, r2, r3, sk + n * (AST * 2) + col);
            uint32_t b0[2] = {r0, r1};
            mma_bf16(c[2 * p], a, b0);
            if (p < 3) {
                uint32_t b1[2] = {r2, r3};
                mma_bf16(c[2 * p + 1], a, b1);
            }
        }
    }

    const int g = lane >> 2, qd = lane & 3;
    const int row0 = wm * 16 + g, row1 = row0 + 8;
    const int rr0 = row0 < NWIN ? row0 : 0;
    const int rr1 = row1 < NWIN ? row1 : 0;
    {
        int ws = w & 255;
        int type = (((ws >> 4) == 15) << 1) | ((ws & 15) == 15);
        const float* btab = bias + (size_t)(type * HEADS + h) * NWIN * BCOL;
        const float* bt0 = btab + rr0 * BCOL + 2 * qd;
        const float* bt1 = btab + rr1 * BCOL + 2 * qd;
#pragma unroll
        for (int tt = 0; tt < 7; tt++) {
            float2 b0 = *(const float2*)&bt0[tt * 8];
            float2 b1 = *(const float2*)&bt1[tt * 8];
            c[tt][0] += b0.x; c[tt][1] += b0.y;
            c[tt][2] += b1.x; c[tt][3] += b1.y;
        }
    }

    {
        float mx = -1e30f;
#pragma unroll
        for (int tt = 0; tt < 7; tt++) mx = fmaxf(mx, fmaxf(c[tt][0], c[tt][1]));
        mx = fmaxf(mx, __shfl_xor_sync(0xffffffffu, mx, 1));
        mx = fmaxf(mx, __shfl_xor_sync(0xffffffffu, mx, 2));
        float sum = 0.f;
#pragma unroll
        for (int tt = 0; tt < 7; tt++) {
            c[tt][0] = __expf(c[tt][0] - mx); sum += c[tt][0];
            c[tt][1] = __expf(c[tt][1] - mx); sum += c[tt][1];
        }
        sum += __shfl_xor_sync(0xffffffffu, sum, 1);
        sum += __shfl_xor_sync(0xffffffffu, sum, 2);
        float inv = 1.0f / sum;
#pragma unroll
        for (int tt = 0; tt < 7; tt++) { c[tt][0] *= inv; c[tt][1] *= inv; }
    }
    {
        float mx = -1e30f;
#pragma unroll
        for (int tt = 0; tt < 7; tt++) mx = fmaxf(mx, fmaxf(c[tt][2], c[tt][3]));
        mx = fmaxf(mx, __shfl_xor_sync(0xffffffffu, mx, 1));
        mx = fmaxf(mx, __shfl_xor_sync(0xffffffffu, mx, 2));
        float sum = 0.f;
#pragma unroll
        for (int tt = 0; tt < 7; tt++) {
            c[tt][2] = __expf(c[tt][2] - mx); sum += c[tt][2];
            c[tt][3] = __expf(c[tt][3] - mx); sum += c[tt][3];
        }
        sum += __shfl_xor_sync(0xffffffffu, sum, 1);
        sum += __shfl_xor_sync(0xffffffffu, sum, 2);
        float inv = 1.0f / sum;
#pragma unroll
        for (int tt = 0; tt < 7; tt++) { c[tt][2] *= inv; c[tt][3] *= inv; }
    }

    float o[4][4] = {};
#pragma unroll
    for (int kc = 0; kc < 4; kc++) {
        uint32_t a[4];
        a[0] = packbf(c[2 * kc][0], c[2 * kc][1]);
        a[1] = packbf(c[2 * kc][2], c[2 * kc][3]);
        if (2 * kc + 1 < 7) {
            a[2] = packbf(c[2 * kc + 1][0], c[2 * kc + 1][1]);
            a[3] = packbf(c[2 * kc + 1][2], c[2 * kc + 1][3]);
        } else {
            a[2] = 0; a[3] = 0;
        }
#pragma unroll
        for (int p = 0; p < 2; p++) {
            int row = kc * 16 + (sub & 1) * 8 + l7;
            int col = p * 32 + (sub >> 1) * 16;
            uint32_t r0, r1, r2, r3;
            ldsm4t(r0, r1, r2, r3, sv + row * (AST * 2) + col);
            uint32_t b0[2] = {r0, r1}, b1[2] = {r2, r3};
            mma_bf16(o[2 * p], a, b0);
            mma_bf16(o[2 * p + 1], a, b1);
        }
    }

    bf16* ob = out + (size_t)w * NWIN * DIM + h * HEADDIM;
    if (row0 < NWIN) {
#pragma unroll
        for (int nt = 0; nt < 4; nt++) {
            __nv_bfloat162 pv = __floats2bfloat162_rn(o[nt][0], o[nt][1]);
            *(__nv_bfloat162*)&ob[(size_t)row0 * DIM + nt * 8 + 2 * qd] = pv;
        }
    }
    if (row1 < NWIN) {
#pragma unroll
        for (int nt = 0; nt < 4; nt++) {
            __nv_bfloat162 pv = __floats2bfloat162_rn(o[nt][2], o[nt][3]);
            *(__nv_bfloat162*)&ob[(size_t)row1 * DIM + nt * 8 + 2 * qd] = pv;
        }
    }
}

// ---------------- launcher ----------------
extern "C" void kernel_launch(void* const* d_in, const int* in_sizes, int n_in,
                              void* d_out, int out_size) {
    const float* x      = (const float*)d_in[0];
    const float* w_qkv  = (const float*)d_in[1];
    const float* b_qkv  = (const float*)d_in[2];
    const float* w_proj = (const float*)d_in[3];
    const float* b_proj = (const float*)d_in[4];
    const float* rpe    = (const float*)d_in[5];
    const float* gamma1 = (const float*)d_in[6];
    const float* beta1  = (const float*)d_in[7];
    const float* gamma2 = (const float*)d_in[8];
    const float* beta2  = (const float*)d_in[9];
    const float* w_fc1  = (const float*)d_in[10];
    const float* b_fc1  = (const float*)d_in[11];
    const float* w_fc2  = (const float*)d_in[12];
    const float* b_fc2  = (const float*)d_in[13];
    float* out = (float*)d_out;

    bf16 *win, *q, *k, *v, *att, *hbuf, *wqkv, *wproj, *wfc1, *wfc2;
    float *x1, *bias;
    cudaGetSymbolAddress((void**)&win,   g_win);
    cudaGetSymbolAddress((void**)&q,     g_q);
    cudaGetSymbolAddress((void**)&k,     g_k);
    cudaGetSymbolAddress((void**)&v,     g_v);
    cudaGetSymbolAddress((void**)&att,   g_att);
    cudaGetSymbolAddress((void**)&x1,    g_x1);
    cudaGetSymbolAddress((void**)&hbuf,  g_h);
    cudaGetSymbolAddress((void**)&wqkv,  g_wqkv);
    cudaGetSymbolAddress((void**)&wproj, g_wproj);
    cudaGetSymbolAddress((void**)&wfc1,  g_wfc1);
    cudaGetSymbolAddress((void**)&wfc2,  g_wfc2);
    cudaGetSymbolAddress((void**)&bias,  g_bias);

    cudaFuncSetAttribute(gemm_bf16<0>, cudaFuncAttributeMaxDynamicSharedMemorySize, GEMM_SMEM);
    cudaFuncSetAttribute(gemm_bf16<1>, cudaFuncAttributeMaxDynamicSharedMemorySize, GEMM_SMEM);
    cudaFuncSetAttribute(gemm_bf16<2>, cudaFuncAttributeMaxDynamicSharedMemorySize, GEMM_SMEM);
    cudaFuncSetAttribute(gemm_bf16<3>, cudaFuncAttributeMaxDynamicSharedMemorySize, GEMM_SMEM);

    // 0) weight conversions + bias table
    cvt_all<<<(N4_ALL + 255) / 256, 256>>>(
        (const float4*)w_qkv, (const float4*)w_proj, (const float4*)w_fc1,
        (const float4*)w_fc2, (__nv_bfloat162*)wqkv, (__nv_bfloat162*)wproj,
        (__nv_bfloat162*)wfc1, (__nv_bfloat162*)wfc2);
    build_bias<<<4 * HEADS, 256>>>(rpe, bias);

    const int LN_BLOCKS = TOKENS / 8;
    const int MT = TOKENS / BM;   // 1568

    // 1) LN1 + shift + window gather
    ln_kernel<true><<<LN_BLOCKS, 256>>>(x, gamma1, beta1, win);

    // 2) QKV GEMM (N=576)
    gemm_bf16<0><<<dim3(576 / BN, MT), 256, GEMM_SMEM>>>(
        win, wqkv, b_qkv, q, k, v, nullptr, TOKENS, 3 * DIM, DIM);

    // 3) windowed attention (mma + bias table)
    attn_kernel<<<BW * HEADS, 128>>>(q, k, v, bias, att);

    // 4) proj GEMM + unshift + residual -> x1 (fp32)
    gemm_bf16<1><<<dim3(DIM / BN, MT), 256, GEMM_SMEM>>>(
        att, wproj, b_proj, x1, nullptr, nullptr, x, TOKENS, DIM, DIM);

    // 5) LN2 -> bf16
    ln_kernel<false><<<LN_BLOCKS, 256>>>(x1, gamma2, beta2, win);

    // 6) fc1 GEMM + GELU (N=768) -> bf16
    gemm_bf16<2><<<dim3(HIDDEN / BN, MT), 256, GEMM_SMEM>>>(
        win, wfc1, b_fc1, hbuf, nullptr, nullptr, nullptr, TOKENS, HIDDEN, DIM);

    // 7) fc2 GEMM + residual(x1) -> fp32 d_out (K=768)
    gemm_bf16<3><<<dim3(DIM / BN, MT), 256, GEMM_SMEM>>>(
        hbuf, wfc2, b_fc2, out, nullptr, nullptr, x1, TOKENS, DIM, HIDDEN);
}

// round 15
// speedup vs baseline: 1.1896x; 1.0047x over previous
#include <cuda_runtime.h>
#include <cuda_bf16.h>
#include <math.h>
#include <stdint.h>

// ---------------- problem constants ----------------
#define BATCH 16
#define HH 112
#define WW 112
#define SS 7
#define DD 3
#define HEADS 6
#define DIM 192
#define HIDDEN 768
#define NWIN 49
#define WIN_PER_IMG 256
#define BW (BATCH * WIN_PER_IMG)   // 4096
#define TOKENS (BW * NWIN)         // 200704
#define HEADDIM 32
#define LPIX (HH * WW)
#define BCOL 56                    // padded bias row stride

typedef __nv_bfloat16 bf16;

// ---------------- scratch ----------------
__device__ bf16  g_win[(size_t)TOKENS * DIM];
__device__ bf16  g_q[(size_t)TOKENS * DIM];
__device__ bf16  g_k[(size_t)TOKENS * DIM];
__device__ bf16  g_v[(size_t)TOKENS * DIM];
__device__ bf16  g_att[(size_t)TOKENS * DIM];
__device__ float g_x1[(size_t)TOKENS * DIM];
__device__ bf16  g_h[(size_t)TOKENS * HIDDEN];
__device__ bf16  g_wqkv[3 * DIM * DIM];
__device__ bf16  g_wproj[DIM * DIM];
__device__ bf16  g_wfc1[HIDDEN * DIM];
__device__ bf16  g_wfc2[DIM * HIDDEN];
__device__ float g_bias[4 * HEADS * NWIN * BCOL];   // rpe+mask bias tables

// ---------------- ptx helpers ----------------
__device__ __forceinline__ uint32_t smem_u32(const void* p) {
    return (uint32_t)__cvta_generic_to_shared(p);
}
__device__ __forceinline__ void cp_async16(uint32_t s, const void* g) {
    asm volatile("cp.async.cg.shared.global [%0], [%1], 16;" :: "r"(s), "l"(g));
}
__device__ __forceinline__ void cp_commit() {
    asm volatile("cp.async.commit_group;");
}
template <int N>
__device__ __forceinline__ void cp_wait() {
    asm volatile("cp.async.wait_group %0;" :: "n"(N));
}
__device__ __forceinline__ void ldsm4(uint32_t& r0, uint32_t& r1, uint32_t& r2,
                                      uint32_t& r3, uint32_t addr) {
    asm volatile("ldmatrix.sync.aligned.m8n8.x4.shared.b16 {%0,%1,%2,%3}, [%4];"
                 : "=r"(r0), "=r"(r1), "=r"(r2), "=r"(r3) : "r"(addr));
}
__device__ __forceinline__ void ldsm4t(uint32_t& r0, uint32_t& r1, uint32_t& r2,
                                       uint32_t& r3, uint32_t addr) {
    asm volatile("ldmatrix.sync.aligned.m8n8.x4.trans.shared.b16 {%0,%1,%2,%3}, [%4];"
                 : "=r"(r0), "=r"(r1), "=r"(r2), "=r"(r3) : "r"(addr));
}
__device__ __forceinline__ void mma_bf16(float* d, const uint32_t* a, const uint32_t* b) {
    asm volatile(
        "mma.sync.aligned.m16n8k16.row.col.f32.bf16.bf16.f32 "
        "{%0,%1,%2,%3}, {%4,%5,%6,%7}, {%8,%9}, {%0,%1,%2,%3};"
        : "+f"(d[0]), "+f"(d[1]), "+f"(d[2]), "+f"(d[3])
        : "r"(a[0]), "r"(a[1]), "r"(a[2]), "r"(a[3]), "r"(b[0]), "r"(b[1]));
}
__device__ __forceinline__ uint32_t packbf(float a, float b) {
    __nv_bfloat162 t = __floats2bfloat162_rn(a, b);
    return *(uint32_t*)&t;
}

// ---------------- weight fp32 -> bf16 convert (all weights, 1 launch) ------
#define N4_QKV (3 * DIM * DIM / 4)
#define N4_PROJ (DIM * DIM / 4)
#define N4_FC1 (HIDDEN * DIM / 4)
#define N4_FC2 (DIM * HIDDEN / 4)
#define N4_ALL (N4_QKV + N4_PROJ + N4_FC1 + N4_FC2)
__global__ void cvt_all(const float4* s0, const float4* s1, const float4* s2,
                        const float4* s3, __nv_bfloat162* d0, __nv_bfloat162* d1,
                        __nv_bfloat162* d2, __nv_bfloat162* d3) {
    int i = blockIdx.x * 256 + threadIdx.x;
    const float4* s; __nv_bfloat162* d; int j = i;
    if (j < N4_QKV) { s = s0; d = d0; }
    else if ((j -= N4_QKV) < N4_PROJ) { s = s1; d = d1; }
    else if ((j -= N4_PROJ) < N4_FC1) { s = s2; d = d2; }
    else if ((j -= N4_FC1) < N4_FC2) { s = s3; d = d3; }
    else return;
    float4 v = s[j];
    d[2 * j]     = __floats2bfloat162_rn(v.x, v.y);
    d[2 * j + 1] = __floats2bfloat162_rn(v.z, v.w);
}

// ---------------- RPE+mask bias tables: 4 window types x 6 heads ----------
__global__ void build_bias(const float* __restrict__ rpe, float* __restrict__ bias) {
    int bt = blockIdx.x;                  // 0..23
    int type = bt / HEADS, h = bt - type * HEADS;
    int rbig = type >> 1, cbig = type & 1;
    const int LT[9] = {0, 5, 4, 7, 8, 6, 2, 3, 1};
    for (int idx = threadIdx.x; idx < NWIN * BCOL; idx += 256) {
        int row = idx / BCOL, col = idx - row * BCOL;
        float v;
        if (col >= NWIN) {
            v = -1e9f;
        } else {
            int ri = row / SS, rj = row - ri * SS;
            int ci = col / SS, cj = col - ci * SS;
            v = rpe[((ri - ci + 6) * 13 + (rj - cj + 6)) * HEADS + h];
            int rb_r = rbig ? (ri < (SS - DD) ? 1 : 2) : 0;
            int cb_r = cbig ? (rj < (SS - DD) ? 1 : 2) : 0;
            int rb_c = rbig ? (ci < (SS - DD) ? 1 : 2) : 0;
            int cb_c = cbig ? (cj < (SS - DD) ? 1 : 2) : 0;
            if (LT[rb_r * 3 + cb_r] != LT[rb_c * 3 + cb_c]) v -= 100.0f;
        }
        bias[(size_t)bt * NWIN * BCOL + idx] = v;
    }
}

// ---------------- LayerNorm (one warp per token), bf16 out ----------------
template <bool GATHER>
__global__ void ln_kernel(const float* __restrict__ x,
                          const float* __restrict__ gamma,
                          const float* __restrict__ beta,
                          bf16* __restrict__ out) {
    int warp = (blockIdx.x * blockDim.x + threadIdx.x) >> 5;
    int lane = threadIdx.x & 31;
    if (warp >= TOKENS) return;

    const float* src;
    if (GATHER) {
        int w = warp / NWIN, n = warp - w * NWIN;
        int b = w >> 8, ws = w & 255;
        int wh = ws >> 4, wc = ws & 15;
        int ii = n / SS, jj = n - ii * SS;
        int r = wh * SS + ii + DD; if (r >= HH) r -= HH;
        int c = wc * SS + jj + DD; if (c >= WW) c -= WW;
        src = x + ((size_t)b * LPIX + r * WW + c) * DIM;
    } else {
        src = x + (size_t)warp * DIM;
    }

    float v[6];
    float s = 0.f, s2 = 0.f;
#pragma unroll
    for (int k = 0; k < 6; k++) {
        v[k] = src[lane + 32 * k];
        s += v[k];
        s2 += v[k] * v[k];
    }
#pragma unroll
    for (int o = 16; o > 0; o >>= 1) {
        s  += __shfl_xor_sync(0xffffffffu, s, o);
        s2 += __shfl_xor_sync(0xffffffffu, s2, o);
    }
    float mu = s * (1.0f / DIM);
    float var = s2 * (1.0f / DIM) - mu * mu;
    float rstd = rsqrtf(var + 1e-5f);
    bf16* dst = out + (size_t)warp * DIM;
#pragma unroll
    for (int k = 0; k < 6; k++) {
        int cc = lane + 32 * k;
        dst[cc] = __float2bfloat16_rn((v[k] - mu) * rstd * gamma[cc] + beta[cc]);
    }
}

// ---------------- bf16 tensor-core GEMM (BN=96, 256 thr, 2 CTA/SM) --------
// Block 128x96x64, 8 warps (4m x 2n), warp tile 32x48.
// 3 smem stages, depth-2 prefetch, ONE __syncthreads per k-chunk,
// fragment double-buffering across ks steps (ldsm of ks+1 hidden under mma of ks).
#define BM 128
#define BN 96
#define A_STAGE 16384
#define B_STAGE 12288
#define STAGE_BYTES (A_STAGE + B_STAGE)       // 28672
#define GEMM_SMEM (3 * STAGE_BYTES)           // 86016

template <int EPI>
__global__ void __launch_bounds__(256, 2)
gemm_bf16(const bf16* __restrict__ A, const bf16* __restrict__ W,
          const float* __restrict__ bias,
          void* __restrict__ O0, void* __restrict__ O1, void* __restrict__ O2,
          const float* __restrict__ RES, int M, int N, int K) {
    extern __shared__ char sm[];
    const int t = threadIdx.x;
    const int wid = t >> 5, lane = t & 31;
    const int warp_m = wid & 3, warp_n = wid >> 2;
    const int m0 = blockIdx.y * BM;
    const int n0 = blockIdx.x * BN;
    const uint32_t sbase = smem_u32(sm);
    const int NT = K >> 6;

    const int lr = lane & 7, g2 = lane >> 3;
    // fragment ldsm base offsets (row part is ks-independent)
    const int a_row0 = warp_m * 32 + lr + (g2 & 1) * 8;
    const int a_coff = (g2 >> 1) * 16;
    const int b_row0 = warp_n * 48 + lr + (g2 >> 1) * 8;
    const int b_coff = (g2 & 1) * 16;

    float acc[2][6][4] = {};

    auto issue = [&](int kt) {
        int s = kt % 3;
        const char* Ab = (const char*)(A + (size_t)m0 * K + kt * 64);
        uint32_t as = sbase + s * STAGE_BYTES;
#pragma unroll
        for (int i = 0; i < 4; i++) {
            int id = i * 256 + t;
            int row = id >> 3, c = id & 7;
            cp_async16(as + row * 128 + ((c * 16) ^ ((row & 7) << 4)),
                       Ab + (size_t)row * K * 2 + c * 16);
        }
        const char* Bb = (const char*)(W + (size_t)n0 * K + kt * 64);
        uint32_t bs = as + A_STAGE;
#pragma unroll
        for (int i = 0; i < 3; i++) {
            int id = i * 256 + t;
            int row = id >> 3, c = id & 7;
            cp_async16(bs + row * 128 + ((c * 16) ^ ((row & 7) << 4)),
                       Bb + (size_t)row * K * 2 + c * 16);
        }
    };

    issue(0); cp_commit();
    if (NT > 1) issue(1);
    cp_commit();

    for (int kt = 0; kt < NT; kt++) {
        cp_wait<1>();
        __syncthreads();
        if (kt + 2 < NT) issue(kt + 2);
        cp_commit();

        int s = kt % 3;
        uint32_t as = sbase + s * STAGE_BYTES;
        uint32_t bs = as + A_STAGE;

        uint32_t a[2][2][4], b[2][6][2];

        // fragment loader for step ks into buffer u
        auto load_frags = [&](int ks, int u) {
            const int kb = ks * 32;
#pragma unroll
            for (int mf = 0; mf < 2; mf++) {
                int row = a_row0 + mf * 16;
                int col = kb + a_coff;
                ldsm4(a[u][mf][0], a[u][mf][1], a[u][mf][2], a[u][mf][3],
                      as + row * 128 + (col ^ ((row & 7) << 4)));
            }
#pragma unroll
            for (int p = 0; p < 3; p++) {
                int row = b_row0 + p * 16;
                int col = kb + b_coff;
                uint32_t r0, r1, r2, r3;
                ldsm4(r0, r1, r2, r3, bs + row * 128 + (col ^ ((row & 7) << 4)));
                b[u][p * 2][0] = r0;     b[u][p * 2][1] = r1;
                b[u][p * 2 + 1][0] = r2; b[u][p * 2 + 1][1] = r3;
            }
        };

        load_frags(0, 0);
#pragma unroll
        for (int ks = 0; ks < 4; ks++) {
            int cur = ks & 1;
            if (ks < 3) load_frags(ks + 1, cur ^ 1);   // hide ldsm under mma below
#pragma unroll
            for (int mf = 0; mf < 2; mf++)
#pragma unroll
                for (int nf = 0; nf < 6; nf++)
                    mma_bf16(acc[mf][nf], a[cur][mf], b[cur][nf]);
        }
    }

    const int gq = lane >> 2, qq = lane & 3;
#pragma unroll
    for (int mf = 0; mf < 2; mf++) {
#pragma unroll
        for (int nf = 0; nf < 6; nf++) {
#pragma unroll
            for (int half = 0; half < 2; half++) {
                int r = m0 + warp_m * 32 + mf * 16 + gq + half * 8;
                int c = n0 + warp_n * 48 + nf * 8 + 2 * qq;
                float v0 = acc[mf][nf][2 * half + 0] + bias[c];
                float v1 = acc[mf][nf][2 * half + 1] + bias[c + 1];
                if (EPI == 0) {
                    int which = c / DIM;
                    int c2 = c - which * DIM;
                    int hd = c2 >> 5, dd = c2 & 31;
                    int w = r / NWIN, n = r - w * NWIN;
                    size_t off = ((size_t)(w * HEADS + hd) * NWIN + n) * HEADDIM + dd;
                    bf16* dst = (which == 0) ? (bf16*)O0 : (which == 1) ? (bf16*)O1 : (bf16*)O2;
                    if (which == 0) { v0 *= 0.17677669529663687f; v1 *= 0.17677669529663687f; }
                    *(__nv_bfloat162*)(dst + off) = __floats2bfloat162_rn(v0, v1);
                } else if (EPI == 1) {
                    int w = r / NWIN, n = r - w * NWIN;
                    int b2 = w >> 8, ws = w & 255;
                    int wh = ws >> 4, wc = ws & 15;
                    int ii = n / SS, jj = n - ii * SS;
                    int rr = wh * SS + ii + DD; if (rr >= HH) rr -= HH;
                    int cc = wc * SS + jj + DD; if (cc >= WW) cc -= WW;
                    size_t dst = ((size_t)b2 * LPIX + rr * WW + cc) * DIM + c;
                    float* o = (float*)O0;
                    o[dst] = v0 + RES[dst];
                    o[dst + 1] = v1 + RES[dst + 1];
                } else if (EPI == 2) {
                    size_t idx = (size_t)r * N + c;
                    float g0 = 0.5f * v0 * (1.0f + erff(v0 * 0.70710678118654752f));
                    float g1 = 0.5f * v1 * (1.0f + erff(v1 * 0.70710678118654752f));
                    *(__nv_bfloat162*)((bf16*)O0 + idx) = __floats2bfloat162_rn(g0, g1);
                } else {
                    size_t idx = (size_t)r * N + c;
                    float* o = (float*)O0;
                    o[idx] = v0 + RES[idx];
                    o[idx + 1] = v1 + RES[idx + 1];
                }
            }
        }
    }
}

// ---------------- attention via mma: one block per (window, head) ----------
#define AST 40
__global__ void __launch_bounds__(128)
attn_kernel(const bf16* __restrict__ q, const bf16* __restrict__ k,
            const bf16* __restrict__ v, const float* __restrict__ bias,
            bf16* __restrict__ out) {
    int bh = blockIdx.x;
    int w = bh / HEADS, h = bh - w * HEADS;

    __shared__ bf16 qs[64 * AST];
    __shared__ bf16 ks[64 * AST];
    __shared__ bf16 vs[64 * AST];

    const int t = threadIdx.x;
    const int wm = t >> 5, lane = t & 31;

    {
        const uint4* qg = (const uint4*)(q + (size_t)bh * NWIN * HEADDIM);
        const uint4* kg = (const uint4*)(k + (size_t)bh * NWIN * HEADDIM);
        const uint4* vg = (const uint4*)(v + (size_t)bh * NWIN * HEADDIM);
        const uint4 zz = make_uint4(0, 0, 0, 0);
#pragma unroll
        for (int it = 0; it < 2; it++) {
            int task = it * 128 + t;
            int row = task >> 2, seg = task & 3;
            bool ok = row < NWIN;
            *(uint4*)&qs[row * AST + seg * 8] = ok ? qg[row * 4 + seg] : zz;
            *(uint4*)&ks[row * AST + seg * 8] = ok ? kg[row * 4 + seg] : zz;
            *(uint4*)&vs[row * AST + seg * 8] = ok ? vg[row * 4 + seg] : zz;
        }
    }
    __syncthreads();

    const uint32_t sq = smem_u32(qs), sk = smem_u32(ks), sv = smem_u32(vs);
    const int sub = lane >> 3, l7 = lane & 7;

    float c[7][4] = {};
#pragma unroll
    for (int kc = 0; kc < 2; kc++) {
        uint32_t a[4];
        {
            int row = wm * 16 + (sub & 1) * 8 + l7;
            int col = kc * 32 + (sub >> 1) * 16;
            ldsm4(a[0], a[1], a[2], a[3], sq + row * (AST * 2) + col);
        }
#pragma unroll
        for (int p = 0; p < 4; p++) {
            int n = p * 16 + (sub >> 1) * 8 + l7;
            int col = kc * 32 + (sub & 1) * 16;
            uint32_t r0, r1, r2, r3;
            ldsm4(r0, r1, r2, r3, sk + n * (AST * 2) + col);
            uint32_t b0[2] = {r0, r1};
            mma_bf16(c[2 * p], a, b0);
            if (p < 3) {
                uint32_t b1[2] = {r2, r3};
                mma_bf16(c[2 * p + 1], a, b1);
            }
        }
    }

    const int g = lane >> 2, qd = lane & 3;
    const int row0 = wm * 16 + g, row1 = row0 + 8;
    const int rr0 = row0 < NWIN ? row0 : 0;
    const int rr1 = row1 < NWIN ? row1 : 0;
    {
        int ws = w & 255;
        int type = (((ws >> 4) == 15) << 1) | ((ws & 15) == 15);
        const float* btab = bias + (size_t)(type * HEADS + h) * NWIN * BCOL;
        const float* bt0 = btab + rr0 * BCOL + 2 * qd;
        const float* bt1 = btab + rr1 * BCOL + 2 * qd;
#pragma unroll
        for (int tt = 0; tt < 7; tt++) {
            float2 b0 = *(const float2*)&bt0[tt * 8];
            float2 b1 = *(const float2*)&bt1[tt * 8];
            c[tt][0] += b0.x; c[tt][1] += b0.y;
            c[tt][2] += b1.x; c[tt][3] += b1.y;
        }
    }

    {
        float mx = -1e30f;
#pragma unroll
        for (int tt = 0; tt < 7; tt++) mx = fmaxf(mx, fmaxf(c[tt][0], c[tt][1]));
        mx = fmaxf(mx, __shfl_xor_sync(0xffffffffu, mx, 1));
        mx = fmaxf(mx, __shfl_xor_sync(0xffffffffu, mx, 2));
        float sum = 0.f;
#pragma unroll
        for (int tt = 0; tt < 7; tt++) {
            c[tt][0] = __expf(c[tt][0] - mx); sum += c[tt][0];
            c[tt][1] = __expf(c[tt][1] - mx); sum += c[tt][1];
        }
        sum += __shfl_xor_sync(0xffffffffu, sum, 1);
        sum += __shfl_xor_sync(0xffffffffu, sum, 2);
        float inv = 1.0f / sum;
#pragma unroll
        for (int tt = 0; tt < 7; tt++) { c[tt][0] *= inv; c[tt][1] *= inv; }
    }
    {
        float mx = -1e30f;
#pragma unroll
        for (int tt = 0; tt < 7; tt++) mx = fmaxf(mx, fmaxf(c[tt][2], c[tt][3]));
        mx = fmaxf(mx, __shfl_xor_sync(0xffffffffu, mx, 1));
        mx = fmaxf(mx, __shfl_xor_sync(0xffffffffu, mx, 2));
        float sum = 0.f;
#pragma unroll
        for (int tt = 0; tt < 7; tt++) {
            c[tt][2] = __expf(c[tt][2] - mx); sum += c[tt][2];
            c[tt][3] = __expf(c[tt][3] - mx); sum += c[tt][3];
        }
        sum += __shfl_xor_sync(0xffffffffu, sum, 1);
        sum += __shfl_xor_sync(0xffffffffu, sum, 2);
        float inv = 1.0f / sum;
#pragma unroll
        for (int tt = 0; tt < 7; tt++) { c[tt][2] *= inv; c[tt][3] *= inv; }
    }

    float o[4][4] = {};
#pragma unroll
    for (int kc = 0; kc < 4; kc++) {
        uint32_t a[4];
        a[0] = packbf(c[2 * kc][0], c[2 * kc][1]);
        a[1] = packbf(c[2 * kc][2], c[2 * kc][3]);
        if (2 * kc + 1 < 7) {
            a[2] = packbf(c[2 * kc + 1][0], c[2 * kc + 1][1]);
            a[3] = packbf(c[2 * kc + 1][2], c[2 * kc + 1][3]);
        } else {
            a[2] = 0; a[3] = 0;
        }
#pragma unroll
        for (int p = 0; p < 2; p++) {
            int row = kc * 16 + (sub & 1) * 8 + l7;
            int col = p * 32 + (sub >> 1) * 16;
            uint32_t r0, r1, r2, r3;
            ldsm4t(r0, r1, r2, r3, sv + row * (AST * 2) + col);
            uint32_t b0[2] = {r0, r1}, b1[2] = {r2, r3};
            mma_bf16(o[2 * p], a, b0);
            mma_bf16(o[2 * p + 1], a, b1);
        }
    }

    bf16* ob = out + (size_t)w * NWIN * DIM + h * HEADDIM;
    if (row0 < NWIN) {
#pragma unroll
        for (int nt = 0; nt < 4; nt++) {
            __nv_bfloat162 pv = __floats2bfloat162_rn(o[nt][0], o[nt][1]);
            *(__nv_bfloat162*)&ob[(size_t)row0 * DIM + nt * 8 + 2 * qd] = pv;
        }
    }
    if (row1 < NWIN) {
#pragma unroll
        for (int nt = 0; nt < 4; nt++) {
            __nv_bfloat162 pv = __floats2bfloat162_rn(o[nt][2], o[nt][3]);
            *(__nv_bfloat162*)&ob[(size_t)row1 * DIM + nt * 8 + 2 * qd] = pv;
        }
    }
}

// ---------------- launcher ----------------
extern "C" void kernel_launch(void* const* d_in, const int* in_sizes, int n_in,
                              void* d_out, int out_size) {
    const float* x      = (const float*)d_in[0];
    const float* w_qkv  = (const float*)d_in[1];
    const float* b_qkv  = (const float*)d_in[2];
    const float* w_proj = (const float*)d_in[3];
    const float* b_proj = (const float*)d_in[4];
    const float* rpe    = (const float*)d_in[5];
    const float* gamma1 = (const float*)d_in[6];
    const float* beta1  = (const float*)d_in[7];
    const float* gamma2 = (const float*)d_in[8];
    const float* beta2  = (const float*)d_in[9];
    const float* w_fc1  = (const float*)d_in[10];
    const float* b_fc1  = (const float*)d_in[11];
    const float* w_fc2  = (const float*)d_in[12];
    const float* b_fc2  = (const float*)d_in[13];
    float* out = (float*)d_out;

    bf16 *win, *q, *k, *v, *att, *hbuf, *wqkv, *wproj, *wfc1, *wfc2;
    float *x1, *bias;
    cudaGetSymbolAddress((void**)&win,   g_win);
    cudaGetSymbolAddress((void**)&q,     g_q);
    cudaGetSymbolAddress((void**)&k,     g_k);
    cudaGetSymbolAddress((void**)&v,     g_v);
    cudaGetSymbolAddress((void**)&att,   g_att);
    cudaGetSymbolAddress((void**)&x1,    g_x1);
    cudaGetSymbolAddress((void**)&hbuf,  g_h);
    cudaGetSymbolAddress((void**)&wqkv,  g_wqkv);
    cudaGetSymbolAddress((void**)&wproj, g_wproj);
    cudaGetSymbolAddress((void**)&wfc1,  g_wfc1);
    cudaGetSymbolAddress((void**)&wfc2,  g_wfc2);
    cudaGetSymbolAddress((void**)&bias,  g_bias);

    cudaFuncSetAttribute(gemm_bf16<0>, cudaFuncAttributeMaxDynamicSharedMemorySize, GEMM_SMEM);
    cudaFuncSetAttribute(gemm_bf16<1>, cudaFuncAttributeMaxDynamicSharedMemorySize, GEMM_SMEM);
    cudaFuncSetAttribute(gemm_bf16<2>, cudaFuncAttributeMaxDynamicSharedMemorySize, GEMM_SMEM);
    cudaFuncSetAttribute(gemm_bf16<3>, cudaFuncAttributeMaxDynamicSharedMemorySize, GEMM_SMEM);

    // 0) weight conversions + bias table
    cvt_all<<<(N4_ALL + 255) / 256, 256>>>(
        (const float4*)w_qkv, (const float4*)w_proj, (const float4*)w_fc1,
        (const float4*)w_fc2, (__nv_bfloat162*)wqkv, (__nv_bfloat162*)wproj,
        (__nv_bfloat162*)wfc1, (__nv_bfloat162*)wfc2);
    build_bias<<<4 * HEADS, 256>>>(rpe, bias);

    const int LN_BLOCKS = TOKENS / 8;
    const int MT = TOKENS / BM;   // 1568

    // 1) LN1 + shift + window gather
    ln_kernel<true><<<LN_BLOCKS, 256>>>(x, gamma1, beta1, win);

    // 2) QKV GEMM (N=576)
    gemm_bf16<0><<<dim3(576 / BN, MT), 256, GEMM_SMEM>>>(
        win, wqkv, b_qkv, q, k, v, nullptr, TOKENS, 3 * DIM, DIM);

    // 3) windowed attention (mma + bias table)
    attn_kernel<<<BW * HEADS, 128>>>(q, k, v, bias, att);

    // 4) proj GEMM + unshift + residual -> x1 (fp32)
    gemm_bf16<1><<<dim3(DIM / BN, MT), 256, GEMM_SMEM>>>(
        att, wproj, b_proj, x1, nullptr, nullptr, x, TOKENS, DIM, DIM);

    // 5) LN2 -> bf16
    ln_kernel<false><<<LN_BLOCKS, 256>>>(x1, gamma2, beta2, win);

    // 6) fc1 GEMM + GELU (N=768) -> bf16
    gemm_bf16<2><<<dim3(HIDDEN / BN, MT), 256, GEMM_SMEM>>>(
        win, wfc1, b_fc1, hbuf, nullptr, nullptr, nullptr, TOKENS, HIDDEN, DIM);

    // 7) fc2 GEMM + residual(x1) -> fp32 d_out (K=768)
    gemm_bf16<3><<<dim3(DIM / BN, MT), 256, GEMM_SMEM>>>(
        hbuf, wfc2, b_fc2, out, nullptr, nullptr, x1, TOKENS, DIM, HIDDEN);
}

// round 16
// speedup vs baseline: 1.1970x; 1.0062x over previous
#include <cuda_runtime.h>
#include <cuda_bf16.h>
#include <math.h>
#include <stdint.h>

// ---------------- problem constants ----------------
#define BATCH 16
#define HH 112
#define WW 112
#define SS 7
#define DD 3
#define HEADS 6
#define DIM 192
#define HIDDEN 768
#define NWIN 49
#define WIN_PER_IMG 256
#define BW (BATCH * WIN_PER_IMG)   // 4096
#define TOKENS (BW * NWIN)         // 200704
#define HEADDIM 32
#define LPIX (HH * WW)
#define BCOL 56                    // padded bias row stride

typedef __nv_bfloat16 bf16;

// ---------------- scratch ----------------
__device__ bf16  g_win[(size_t)TOKENS * DIM];
__device__ bf16  g_q[(size_t)TOKENS * DIM];
__device__ bf16  g_k[(size_t)TOKENS * DIM];
__device__ bf16  g_v[(size_t)TOKENS * DIM];
__device__ bf16  g_att[(size_t)TOKENS * DIM];
__device__ float g_x1[(size_t)TOKENS * DIM];
__device__ bf16  g_h[(size_t)TOKENS * HIDDEN];
__device__ bf16  g_wqkv[3 * DIM * DIM];
__device__ bf16  g_wproj[DIM * DIM];
__device__ bf16  g_wfc1[HIDDEN * DIM];
__device__ bf16  g_wfc2[DIM * HIDDEN];
__device__ float g_bias[4 * HEADS * NWIN * BCOL];   // rpe+mask bias tables

// ---------------- ptx helpers ----------------
__device__ __forceinline__ uint32_t smem_u32(const void* p) {
    return (uint32_t)__cvta_generic_to_shared(p);
}
__device__ __forceinline__ void cp_async16(uint32_t s, const void* g) {
    asm volatile("cp.async.cg.shared.global [%0], [%1], 16;" :: "r"(s), "l"(g));
}
__device__ __forceinline__ void cp_commit() {
    asm volatile("cp.async.commit_group;");
}
template <int N>
__device__ __forceinline__ void cp_wait() {
    asm volatile("cp.async.wait_group %0;" :: "n"(N));
}
__device__ __forceinline__ void ldsm4(uint32_t& r0, uint32_t& r1, uint32_t& r2,
                                      uint32_t& r3, uint32_t addr) {
    asm volatile("ldmatrix.sync.aligned.m8n8.x4.shared.b16 {%0,%1,%2,%3}, [%4];"
                 : "=r"(r0), "=r"(r1), "=r"(r2), "=r"(r3) : "r"(addr));
}
__device__ __forceinline__ void ldsm4t(uint32_t& r0, uint32_t& r1, uint32_t& r2,
                                       uint32_t& r3, uint32_t addr) {
    asm volatile("ldmatrix.sync.aligned.m8n8.x4.trans.shared.b16 {%0,%1,%2,%3}, [%4];"
                 : "=r"(r0), "=r"(r1), "=r"(r2), "=r"(r3) : "r"(addr));
}
__device__ __forceinline__ void mma_bf16(float* d, const uint32_t* a, const uint32_t* b) {
    asm volatile(
        "mma.sync.aligned.m16n8k16.row.col.f32.bf16.bf16.f32 "
        "{%0,%1,%2,%3}, {%4,%5,%6,%7}, {%8,%9}, {%0,%1,%2,%3};"
        : "+f"(d[0]), "+f"(d[1]), "+f"(d[2]), "+f"(d[3])
        : "r"(a[0]), "r"(a[1]), "r"(a[2]), "r"(a[3]), "r"(b[0]), "r"(b[1]));
}
__device__ __forceinline__ uint32_t packbf(float a, float b) {
    __nv_bfloat162 t = __floats2bfloat162_rn(a, b);
    return *(uint32_t*)&t;
}

// ---------------- weight fp32 -> bf16 convert (all weights, 1 launch) ------
#define N4_QKV (3 * DIM * DIM / 4)
#define N4_PROJ (DIM * DIM / 4)
#define N4_FC1 (HIDDEN * DIM / 4)
#define N4_FC2 (DIM * HIDDEN / 4)
#define N4_ALL (N4_QKV + N4_PROJ + N4_FC1 + N4_FC2)
__global__ void cvt_all(const float4* s0, const float4* s1, const float4* s2,
                        const float4* s3, __nv_bfloat162* d0, __nv_bfloat162* d1,
                        __nv_bfloat162* d2, __nv_bfloat162* d3) {
    int i = blockIdx.x * 256 + threadIdx.x;
    const float4* s; __nv_bfloat162* d; int j = i;
    if (j < N4_QKV) { s = s0; d = d0; }
    else if ((j -= N4_QKV) < N4_PROJ) { s = s1; d = d1; }
    else if ((j -= N4_PROJ) < N4_FC1) { s = s2; d = d2; }
    else if ((j -= N4_FC1) < N4_FC2) { s = s3; d = d3; }
    else return;
    float4 v = s[j];
    d[2 * j]     = __floats2bfloat162_rn(v.x, v.y);
    d[2 * j + 1] = __floats2bfloat162_rn(v.z, v.w);
}

// ---------------- RPE+mask bias tables: 4 window types x 6 heads ----------
__global__ void build_bias(const float* __restrict__ rpe, float* __restrict__ bias) {
    int bt = blockIdx.x;                  // 0..23
    int type = bt / HEADS, h = bt - type * HEADS;
    int rbig = type >> 1, cbig = type & 1;
    const int LT[9] = {0, 5, 4, 7, 8, 6, 2, 3, 1};
    for (int idx = threadIdx.x; idx < NWIN * BCOL; idx += 256) {
        int row = idx / BCOL, col = idx - row * BCOL;
        float v;
        if (col >= NWIN) {
            v = -1e9f;
        } else {
            int ri = row / SS, rj = row - ri * SS;
            int ci = col / SS, cj = col - ci * SS;
            v = rpe[((ri - ci + 6) * 13 + (rj - cj + 6)) * HEADS + h];
            int rb_r = rbig ? (ri < (SS - DD) ? 1 : 2) : 0;
            int cb_r = cbig ? (rj < (SS - DD) ? 1 : 2) : 0;
            int rb_c = rbig ? (ci < (SS - DD) ? 1 : 2) : 0;
            int cb_c = cbig ? (cj < (SS - DD) ? 1 : 2) : 0;
            if (LT[rb_r * 3 + cb_r] != LT[rb_c * 3 + cb_c]) v -= 100.0f;
        }
        bias[(size_t)bt * NWIN * BCOL + idx] = v;
    }
}

// ---------------- LayerNorm (one warp per token), bf16 out ----------------
template <bool GATHER>
__global__ void ln_kernel(const float* __restrict__ x,
                          const float* __restrict__ gamma,
                          const float* __restrict__ beta,
                          bf16* __restrict__ out) {
    int warp = (blockIdx.x * blockDim.x + threadIdx.x) >> 5;
    int lane = threadIdx.x & 31;
    if (warp >= TOKENS) return;

    const float* src;
    if (GATHER) {
        int w = warp / NWIN, n = warp - w * NWIN;
        int b = w >> 8, ws = w & 255;
        int wh = ws >> 4, wc = ws & 15;
        int ii = n / SS, jj = n - ii * SS;
        int r = wh * SS + ii + DD; if (r >= HH) r -= HH;
        int c = wc * SS + jj + DD; if (c >= WW) c -= WW;
        src = x + ((size_t)b * LPIX + r * WW + c) * DIM;
    } else {
        src = x + (size_t)warp * DIM;
    }

    float v[6];
    float s = 0.f, s2 = 0.f;
#pragma unroll
    for (int k = 0; k < 6; k++) {
        v[k] = src[lane + 32 * k];
        s += v[k];
        s2 += v[k] * v[k];
    }
#pragma unroll
    for (int o = 16; o > 0; o >>= 1) {
        s  += __shfl_xor_sync(0xffffffffu, s, o);
        s2 += __shfl_xor_sync(0xffffffffu, s2, o);
    }
    float mu = s * (1.0f / DIM);
    float var = s2 * (1.0f / DIM) - mu * mu;
    float rstd = rsqrtf(var + 1e-5f);
    bf16* dst = out + (size_t)warp * DIM;
#pragma unroll
    for (int k = 0; k < 6; k++) {
        int cc = lane + 32 * k;
        dst[cc] = __float2bfloat16_rn((v[k] - mu) * rstd * gamma[cc] + beta[cc]);
    }
}

// ---------------- bf16 tensor-core GEMM (BN=96, 256 thr, 2 CTA/SM) --------
// Block 128x96x64, 8 warps (4m x 2n), warp tile 32x48.
// 3 smem stages, depth-2 prefetch, ONE __syncthreads per k-chunk,
// fragment double-buffering across ks steps.
#define BM 128
#define BN 96
#define A_STAGE 16384
#define B_STAGE 12288
#define STAGE_BYTES (A_STAGE + B_STAGE)       // 28672
#define GEMM_SMEM (3 * STAGE_BYTES)           // 86016

template <int EPI>
__global__ void __launch_bounds__(256, 2)
gemm_bf16(const bf16* __restrict__ A, const bf16* __restrict__ W,
          const float* __restrict__ bias,
          void* __restrict__ O0, void* __restrict__ O1, void* __restrict__ O2,
          const float* __restrict__ RES, int M, int N, int K) {
    extern __shared__ char sm[];
    const int t = threadIdx.x;
    const int wid = t >> 5, lane = t & 31;
    const int warp_m = wid & 3, warp_n = wid >> 2;
    const int m0 = blockIdx.y * BM;
    const int n0 = blockIdx.x * BN;
    const uint32_t sbase = smem_u32(sm);
    const int NT = K >> 6;

    const int lr = lane & 7, g2 = lane >> 3;
    const int a_row0 = warp_m * 32 + lr + (g2 & 1) * 8;
    const int a_coff = (g2 >> 1) * 16;
    const int b_row0 = warp_n * 48 + lr + (g2 >> 1) * 8;
    const int b_coff = (g2 & 1) * 16;

    float acc[2][6][4] = {};

    auto issue = [&](int kt) {
        int s = kt % 3;
        const char* Ab = (const char*)(A + (size_t)m0 * K + kt * 64);
        uint32_t as = sbase + s * STAGE_BYTES;
#pragma unroll
        for (int i = 0; i < 4; i++) {
            int id = i * 256 + t;
            int row = id >> 3, c = id & 7;
            cp_async16(as + row * 128 + ((c * 16) ^ ((row & 7) << 4)),
                       Ab + (size_t)row * K * 2 + c * 16);
        }
        const char* Bb = (const char*)(W + (size_t)n0 * K + kt * 64);
        uint32_t bs = as + A_STAGE;
#pragma unroll
        for (int i = 0; i < 3; i++) {
            int id = i * 256 + t;
            int row = id >> 3, c = id & 7;
            cp_async16(bs + row * 128 + ((c * 16) ^ ((row & 7) << 4)),
                       Bb + (size_t)row * K * 2 + c * 16);
        }
    };

    issue(0); cp_commit();
    if (NT > 1) issue(1);
    cp_commit();

    for (int kt = 0; kt < NT; kt++) {
        cp_wait<1>();
        __syncthreads();
        if (kt + 2 < NT) issue(kt + 2);
        cp_commit();

        int s = kt % 3;
        uint32_t as = sbase + s * STAGE_BYTES;
        uint32_t bs = as + A_STAGE;

        uint32_t a[2][2][4], b[2][6][2];
        auto load_frags = [&](int ks, int u) {
            const int kb = ks * 32;
#pragma unroll
            for (int mf = 0; mf < 2; mf++) {
                int row = a_row0 + mf * 16;
                int col = kb + a_coff;
                ldsm4(a[u][mf][0], a[u][mf][1], a[u][mf][2], a[u][mf][3],
                      as + row * 128 + (col ^ ((row & 7) << 4)));
            }
#pragma unroll
            for (int p = 0; p < 3; p++) {
                int row = b_row0 + p * 16;
                int col = kb + b_coff;
                uint32_t r0, r1, r2, r3;
                ldsm4(r0, r1, r2, r3, bs + row * 128 + (col ^ ((row & 7) << 4)));
                b[u][p * 2][0] = r0;     b[u][p * 2][1] = r1;
                b[u][p * 2 + 1][0] = r2; b[u][p * 2 + 1][1] = r3;
            }
        };

        load_frags(0, 0);
#pragma unroll
        for (int ks = 0; ks < 4; ks++) {
            int cur = ks & 1;
            if (ks < 3) load_frags(ks + 1, cur ^ 1);
#pragma unroll
            for (int mf = 0; mf < 2; mf++)
#pragma unroll
                for (int nf = 0; nf < 6; nf++)
                    mma_bf16(acc[mf][nf], a[cur][mf], b[cur][nf]);
        }
    }

    const int gq = lane >> 2, qq = lane & 3;
#pragma unroll
    for (int mf = 0; mf < 2; mf++) {
#pragma unroll
        for (int nf = 0; nf < 6; nf++) {
#pragma unroll
            for (int half = 0; half < 2; half++) {
                int r = m0 + warp_m * 32 + mf * 16 + gq + half * 8;
                int c = n0 + warp_n * 48 + nf * 8 + 2 * qq;
                float v0 = acc[mf][nf][2 * half + 0] + bias[c];
                float v1 = acc[mf][nf][2 * half + 1] + bias[c + 1];
                if (EPI == 0) {
                    int which = c / DIM;
                    int c2 = c - which * DIM;
                    int hd = c2 >> 5, dd = c2 & 31;
                    int w = r / NWIN, n = r - w * NWIN;
                    size_t off = ((size_t)(w * HEADS + hd) * NWIN + n) * HEADDIM + dd;
                    bf16* dst = (which == 0) ? (bf16*)O0 : (which == 1) ? (bf16*)O1 : (bf16*)O2;
                    if (which == 0) { v0 *= 0.17677669529663687f; v1 *= 0.17677669529663687f; }
                    *(__nv_bfloat162*)(dst + off) = __floats2bfloat162_rn(v0, v1);
                } else if (EPI == 2) {
                    size_t idx = (size_t)r * N + c;
                    float g0 = 0.5f * v0 * (1.0f + erff(v0 * 0.70710678118654752f));
                    float g1 = 0.5f * v1 * (1.0f + erff(v1 * 0.70710678118654752f));
                    *(__nv_bfloat162*)((bf16*)O0 + idx) = __floats2bfloat162_rn(g0, g1);
                } else {
                    size_t idx = (size_t)r * N + c;
                    float* o = (float*)O0;
                    o[idx] = v0 + RES[idx];
                    o[idx + 1] = v1 + RES[idx + 1];
                }
            }
        }
    }
}

// ---------------- proj GEMM + unshift + residual + fused LN2 ---------------
// Block 64x192x64, 8 warps (2m x 4n), warp tile 32x48. Full 192-col rows per
// CTA -> LN2 computed in epilogue. Writes x1 (fp32, image layout) AND
// win = LN(x1) (bf16, image-token order).
#define PBM 64
#define PA_STAGE 8192            // 64 rows * 128B
#define PB_STAGE 24576           // 192 rows * 128B
#define PSTAGE_BYTES (PA_STAGE + PB_STAGE)    // 32768
#define PROJ_SMEM (3 * PSTAGE_BYTES)          // 98304

__global__ void __launch_bounds__(256, 2)
gemm_proj_ln(const bf16* __restrict__ A, const bf16* __restrict__ W,
             const float* __restrict__ bias, const float* __restrict__ X,
             const float* __restrict__ gamma, const float* __restrict__ beta,
             float* __restrict__ X1, bf16* __restrict__ WIN) {
    extern __shared__ char sm[];
    const int K = DIM;           // 192
    const int t = threadIdx.x;
    const int wid = t >> 5, lane = t & 31;
    const int warp_m = wid & 1, warp_n = wid >> 1;   // 2m x 4n
    const int m0 = blockIdx.y * PBM;
    const uint32_t sbase = smem_u32(sm);
    const int NT = 3;

    const int lr = lane & 7, g2 = lane >> 3;
    const int a_row0 = warp_m * 32 + lr + (g2 & 1) * 8;
    const int a_coff = (g2 >> 1) * 16;
    const int b_row0 = warp_n * 48 + lr + (g2 >> 1) * 8;
    const int b_coff = (g2 & 1) * 16;

    float acc[2][6][4] = {};

    auto issue = [&](int kt) {
        int s = kt % 3;
        const char* Ab = (const char*)(A + (size_t)m0 * K + kt * 64);
        uint32_t as = sbase + s * PSTAGE_BYTES;
#pragma unroll
        for (int i = 0; i < 2; i++) {
            int id = i * 256 + t;
            int row = id >> 3, c = id & 7;
            cp_async16(as + row * 128 + ((c * 16) ^ ((row & 7) << 4)),
                       Ab + (size_t)row * K * 2 + c * 16);
        }
        const char* Bb = (const char*)(W + kt * 64);
        uint32_t bs = as + PA_STAGE;
#pragma unroll
        for (int i = 0; i < 6; i++) {
            int id = i * 256 + t;
            int row = id >> 3, c = id & 7;
            cp_async16(bs + row * 128 + ((c * 16) ^ ((row & 7) << 4)),
                       Bb + (size_t)row * K * 2 + c * 16);
        }
    };

    issue(0); cp_commit();
    issue(1); cp_commit();

    for (int kt = 0; kt < NT; kt++) {
        cp_wait<1>();
        __syncthreads();
        if (kt + 2 < NT) issue(kt + 2);
        cp_commit();

        int s = kt % 3;
        uint32_t as = sbase + s * PSTAGE_BYTES;
        uint32_t bs = as + PA_STAGE;

        uint32_t a[2][2][4], b[2][6][2];
        auto load_frags = [&](int ks, int u) {
            const int kb = ks * 32;
#pragma unroll
            for (int mf = 0; mf < 2; mf++) {
                int row = a_row0 + mf * 16;
                int col = kb + a_coff;
                ldsm4(a[u][mf][0], a[u][mf][1], a[u][mf][2], a[u][mf][3],
                      as + row * 128 + (col ^ ((row & 7) << 4)));
            }
#pragma unroll
            for (int p = 0; p < 3; p++) {
                int row = b_row0 + p * 16;
                int col = kb + b_coff;
                uint32_t r0, r1, r2, r3;
                ldsm4(r0, r1, r2, r3, bs + row * 128 + (col ^ ((row & 7) << 4)));
                b[u][p * 2][0] = r0;     b[u][p * 2][1] = r1;
                b[u][p * 2 + 1][0] = r2; b[u][p * 2 + 1][1] = r3;
            }
        };

        load_frags(0, 0);
#pragma unroll
        for (int ks = 0; ks < 4; ks++) {
            int cur = ks & 1;
            if (ks < 3) load_frags(ks + 1, cur ^ 1);
#pragma unroll
            for (int mf = 0; mf < 2; mf++)
#pragma unroll
                for (int nf = 0; nf < 6; nf++)
                    mma_bf16(acc[mf][nf], a[cur][mf], b[cur][nf]);
        }
    }

    __syncthreads();   // stage smem dead; reuse for LN partials
    float2* part = (float2*)sm;   // [64][4]

    const int gq = lane >> 2, qq = lane & 3;
    const int cbase = warp_n * 48;

    // per (mf, half): compute val = acc + bias + res, write x1, accumulate LN partials
    size_t itok[2][2];   // image-token index per (mf, half)
#pragma unroll
    for (int mf = 0; mf < 2; mf++) {
#pragma unroll
        for (int half = 0; half < 2; half++) {
            int rl = warp_m * 32 + mf * 16 + gq + half * 8;
            int r = m0 + rl;
            // window-token -> image pixel (unshift)
            int w = r / NWIN, n = r - w * NWIN;
            int b2 = w >> 8, ws = w & 255;
            int wh = ws >> 4, wc = ws & 15;
            int ii = n / SS, jj = n - ii * SS;
            int rr = wh * SS + ii + DD; if (rr >= HH) rr -= HH;
            int cc = wc * SS + jj + DD; if (cc >= WW) cc -= WW;
            size_t it = (size_t)b2 * LPIX + rr * WW + cc;
            itok[mf][half] = it;

            float s = 0.f, s2 = 0.f;
#pragma unroll
            for (int nf = 0; nf < 6; nf++) {
                int c = cbase + nf * 8 + 2 * qq;
                size_t dst = it * DIM + c;
                float v0 = acc[mf][nf][2 * half + 0] + bias[c]     + X[dst];
                float v1 = acc[mf][nf][2 * half + 1] + bias[c + 1] + X[dst + 1];
                acc[mf][nf][2 * half + 0] = v0;
                acc[mf][nf][2 * half + 1] = v1;
                X1[dst] = v0; X1[dst + 1] = v1;
                s += v0 + v1;
                s2 += v0 * v0 + v1 * v1;
            }
            // reduce over qq lanes (xor 1, 2)
            s  += __shfl_xor_sync(0xffffffffu, s, 1);
            s2 += __shfl_xor_sync(0xffffffffu, s2, 1);
            s  += __shfl_xor_sync(0xffffffffu, s, 2);
            s2 += __shfl_xor_sync(0xffffffffu, s2, 2);
            if (qq == 0) part[rl * 4 + warp_n] = make_float2(s, s2);
        }
    }
    __syncthreads();

    // finish LN per row, write win
#pragma unroll
    for (int mf = 0; mf < 2; mf++) {
#pragma unroll
        for (int half = 0; half < 2; half++) {
            int rl = warp_m * 32 + mf * 16 + gq + half * 8;
            float2 p0 = part[rl * 4 + 0], p1 = part[rl * 4 + 1];
            float2 p2 = part[rl * 4 + 2], p3 = part[rl * 4 + 3];
            float s = p0.x + p1.x + p2.x + p3.x;
            float s2 = p0.y + p1.y + p2.y + p3.y;
            float mu = s * (1.0f / DIM);
            float var = s2 * (1.0f / DIM) - mu * mu;
            float rstd = rsqrtf(var + 1e-5f);
            bf16* wr = WIN + itok[mf][half] * DIM;
#pragma unroll
            for (int nf = 0; nf < 6; nf++) {
                int c = cbase + nf * 8 + 2 * qq;
                float v0 = (acc[mf][nf][2 * half + 0] - mu) * rstd * gamma[c] + beta[c];
                float v1 = (acc[mf][nf][2 * half + 1] - mu) * rstd * gamma[c + 1] + beta[c + 1];
                *(__nv_bfloat162*)(wr + c) = __floats2bfloat162_rn(v0, v1);
            }
        }
    }
}

// ---------------- attention via mma: one block per (window, head) ----------
#define AST 40
__global__ void __launch_bounds__(128)
attn_kernel(const bf16* __restrict__ q, const bf16* __restrict__ k,
            const bf16* __restrict__ v, const float* __restrict__ bias,
            bf16* __restrict__ out) {
    int bh = blockIdx.x;
    int w = bh / HEADS, h = bh - w * HEADS;

    __shared__ bf16 qs[64 * AST];
    __shared__ bf16 ks[64 * AST];
    __shared__ bf16 vs[64 * AST];

    const int t = threadIdx.x;
    const int wm = t >> 5, lane = t & 31;

    {
        const uint4* qg = (const uint4*)(q + (size_t)bh * NWIN * HEADDIM);
        const uint4* kg = (const uint4*)(k + (size_t)bh * NWIN * HEADDIM);
        const uint4* vg = (const uint4*)(v + (size_t)bh * NWIN * HEADDIM);
        const uint4 zz = make_uint4(0, 0, 0, 0);
#pragma unroll
        for (int it = 0; it < 2; it++) {
            int task = it * 128 + t;
            int row = task >> 2, seg = task & 3;
            bool ok = row < NWIN;
            *(uint4*)&qs[row * AST + seg * 8] = ok ? qg[row * 4 + seg] : zz;
            *(uint4*)&ks[row * AST + seg * 8] = ok ? kg[row * 4 + seg] : zz;
            *(uint4*)&vs[row * AST + seg * 8] = ok ? vg[row * 4 + seg] : zz;
        }
    }
    __syncthreads();

    const uint32_t sq = smem_u32(qs), sk = smem_u32(ks), sv = smem_u32(vs);
    const int sub = lane >> 3, l7 = lane & 7;

    float c[7][4] = {};
#pragma unroll
    for (int kc = 0; kc < 2; kc++) {
        uint32_t a[4];
        {
            int row = wm * 16 + (sub & 1) * 8 + l7;
            int col = kc * 32 + (sub >> 1) * 16;
            ldsm4(a[0], a[1], a[2], a[3], sq + row * (AST * 2) + col);
        }
#pragma unroll
        for (int p = 0; p < 4; p++) {
            int n = p * 16 + (sub >> 1) * 8 + l7;
            int col = kc * 32 + (sub & 1) * 16;
            uint32_t r0, r1, r2, r3;
            ldsm4(r0, r1, r2, r3, sk + n * (AST * 2) + col);
            uint32_t b0[2] = {r0, r1};
            mma_bf16(c[2 * p], a, b0);
            if (p < 3) {
                uint32_t b1[2] = {r2, r3};
                mma_bf16(c[2 * p + 1], a, b1);
            }
        }
    }

    const int g = lane >> 2, qd = lane & 3;
    const int row0 = wm * 16 + g, row1 = row0 + 8;
    const int rr0 = row0 < NWIN ? row0 : 0;
    const int rr1 = row1 < NWIN ? row1 : 0;
    {
        int ws = w & 255;
        int type = (((ws >> 4) == 15) << 1) | ((ws & 15) == 15);
        const float* btab = bias + (size_t)(type * HEADS + h) * NWIN * BCOL;
        const float* bt0 = btab + rr0 * BCOL + 2 * qd;
        const float* bt1 = btab + rr1 * BCOL + 2 * qd;
#pragma unroll
        for (int tt = 0; tt < 7; tt++) {
            float2 b0 = *(const float2*)&bt0[tt * 8];
            float2 b1 = *(const float2*)&bt1[tt * 8];
            c[tt][0] += b0.x; c[tt][1] += b0.y;
            c[tt][2] += b1.x; c[tt][3] += b1.y;
        }
    }

    {
        float mx = -1e30f;
#pragma unroll
        for (int tt = 0; tt < 7; tt++) mx = fmaxf(mx, fmaxf(c[tt][0], c[tt][1]));
        mx = fmaxf(mx, __shfl_xor_sync(0xffffffffu, mx, 1));
        mx = fmaxf(mx, __shfl_xor_sync(0xffffffffu, mx, 2));
        float sum = 0.f;
#pragma unroll
        for (int tt = 0; tt < 7; tt++) {
            c[tt][0] = __expf(c[tt][0] - mx); sum += c[tt][0];
            c[tt][1] = __expf(c[tt][1] - mx); sum += c[tt][1];
        }
        sum += __shfl_xor_sync(0xffffffffu, sum, 1);
        sum += __shfl_xor_sync(0xffffffffu, sum, 2);
        float inv = 1.0f / sum;
#pragma unroll
        for (int tt = 0; tt < 7; tt++) { c[tt][0] *= inv; c[tt][1] *= inv; }
    }
    {
        float mx = -1e30f;
#pragma unroll
        for (int tt = 0; tt < 7; tt++) mx = fmaxf(mx, fmaxf(c[tt][2], c[tt][3]));
        mx = fmaxf(mx, __shfl_xor_sync(0xffffffffu, mx, 1));
        mx = fmaxf(mx, __shfl_xor_sync(0xffffffffu, mx, 2));
        float sum = 0.f;
#pragma unroll
        for (int tt = 0; tt < 7; tt++) {
            c[tt][2] = __expf(c[tt][2] - mx); sum += c[tt][2];
            c[tt][3] = __expf(c[tt][3] - mx); sum += c[tt][3];
        }
        sum += __shfl_xor_sync(0xffffffffu, sum, 1);
        sum += __shfl_xor_sync(0xffffffffu, sum, 2);
        float inv = 1.0f / sum;
#pragma unroll
        for (int tt = 0; tt < 7; tt++) { c[tt][2] *= inv; c[tt][3] *= inv; }
    }

    float o[4][4] = {};
#pragma unroll
    for (int kc = 0; kc < 4; kc++) {
        uint32_t a[4];
        a[0] = packbf(c[2 * kc][0], c[2 * kc][1]);
        a[1] = packbf(c[2 * kc][2], c[2 * kc][3]);
        if (2 * kc + 1 < 7) {
            a[2] = packbf(c[2 * kc + 1][0], c[2 * kc + 1][1]);
            a[3] = packbf(c[2 * kc + 1][2], c[2 * kc + 1][3]);
        } else {
            a[2] = 0; a[3] = 0;
        }
#pragma unroll
        for (int p = 0; p < 2; p++) {
            int row = kc * 16 + (sub & 1) * 8 + l7;
            int col = p * 32 + (sub >> 1) * 16;
            uint32_t r0, r1, r2, r3;
            ldsm4t(r0, r1, r2, r3, sv + row * (AST * 2) + col);
            uint32_t b0[2] = {r0, r1}, b1[2] = {r2, r3};
            mma_bf16(o[2 * p], a, b0);
            mma_bf16(o[2 * p + 1], a, b1);
        }
    }

    bf16* ob = out + (size_t)w * NWIN * DIM + h * HEADDIM;
    if (row0 < NWIN) {
#pragma unroll
        for (int nt = 0; nt < 4; nt++) {
            __nv_bfloat162 pv = __floats2bfloat162_rn(o[nt][0], o[nt][1]);
            *(__nv_bfloat162*)&ob[(size_t)row0 * DIM + nt * 8 + 2 * qd] = pv;
        }
    }
    if (row1 < NWIN) {
#pragma unroll
        for (int nt = 0; nt < 4; nt++) {
            __nv_bfloat162 pv = __floats2bfloat162_rn(o[nt][2], o[nt][3]);
            *(__nv_bfloat162*)&ob[(size_t)row1 * DIM + nt * 8 + 2 * qd] = pv;
        }
    }
}

// ---------------- launcher ----------------
extern "C" void kernel_launch(void* const* d_in, const int* in_sizes, int n_in,
                              void* d_out, int out_size) {
    const float* x      = (const float*)d_in[0];
    const float* w_qkv  = (const float*)d_in[1];
    const float* b_qkv  = (const float*)d_in[2];
    const float* w_proj = (const float*)d_in[3];
    const float* b_proj = (const float*)d_in[4];
    const float* rpe    = (const float*)d_in[5];
    const float* gamma1 = (const float*)d_in[6];
    const float* beta1  = (const float*)d_in[7];
    const float* gamma2 = (const float*)d_in[8];
    const float* beta2  = (const float*)d_in[9];
    const float* w_fc1  = (const float*)d_in[10];
    const float* b_fc1  = (const float*)d_in[11];
    const float* w_fc2  = (const float*)d_in[12];
    const float* b_fc2  = (const float*)d_in[13];
    float* out = (float*)d_out;

    bf16 *win, *q, *k, *v, *att, *hbuf, *wqkv, *wproj, *wfc1, *wfc2;
    float *x1, *bias;
    cudaGetSymbolAddress((void**)&win,   g_win);
    cudaGetSymbolAddress((void**)&q,     g_q);
    cudaGetSymbolAddress((void**)&k,     g_k);
    cudaGetSymbolAddress((void**)&v,     g_v);
    cudaGetSymbolAddress((void**)&att,   g_att);
    cudaGetSymbolAddress((void**)&x1,    g_x1);
    cudaGetSymbolAddress((void**)&hbuf,  g_h);
    cudaGetSymbolAddress((void**)&wqkv,  g_wqkv);
    cudaGetSymbolAddress((void**)&wproj, g_wproj);
    cudaGetSymbolAddress((void**)&wfc1,  g_wfc1);
    cudaGetSymbolAddress((void**)&wfc2,  g_wfc2);
    cudaGetSymbolAddress((void**)&bias,  g_bias);

    cudaFuncSetAttribute(gemm_bf16<0>, cudaFuncAttributeMaxDynamicSharedMemorySize, GEMM_SMEM);
    cudaFuncSetAttribute(gemm_bf16<2>, cudaFuncAttributeMaxDynamicSharedMemorySize, GEMM_SMEM);
    cudaFuncSetAttribute(gemm_bf16<3>, cudaFuncAttributeMaxDynamicSharedMemorySize, GEMM_SMEM);
    cudaFuncSetAttribute(gemm_proj_ln, cudaFuncAttributeMaxDynamicSharedMemorySize, PROJ_SMEM);

    // 0) weight conversions + bias table
    cvt_all<<<(N4_ALL + 255) / 256, 256>>>(
        (const float4*)w_qkv, (const float4*)w_proj, (const float4*)w_fc1,
        (const float4*)w_fc2, (__nv_bfloat162*)wqkv, (__nv_bfloat162*)wproj,
        (__nv_bfloat162*)wfc1, (__nv_bfloat162*)wfc2);
    build_bias<<<4 * HEADS, 256>>>(rpe, bias);

    const int LN_BLOCKS = TOKENS / 8;
    const int MT = TOKENS / BM;   // 1568

    // 1) LN1 + shift + window gather
    ln_kernel<true><<<LN_BLOCKS, 256>>>(x, gamma1, beta1, win);

    // 2) QKV GEMM (N=576)
    gemm_bf16<0><<<dim3(576 / BN, MT), 256, GEMM_SMEM>>>(
        win, wqkv, b_qkv, q, k, v, nullptr, TOKENS, 3 * DIM, DIM);

    // 3) windowed attention (mma + bias table)
    attn_kernel<<<BW * HEADS, 128>>>(q, k, v, bias, att);

    // 4) proj GEMM + unshift + residual + fused LN2 -> x1 (fp32) + win (bf16)
    gemm_proj_ln<<<dim3(1, TOKENS / PBM), 256, PROJ_SMEM>>>(
        att, wproj, b_proj, x, gamma2, beta2, x1, win);

    // 5) fc1 GEMM + GELU (N=768) -> bf16
    gemm_bf16<2><<<dim3(HIDDEN / BN, MT), 256, GEMM_SMEM>>>(
        win, wfc1, b_fc1, hbuf, nullptr, nullptr, nullptr, TOKENS, HIDDEN, DIM);

    // 6) fc2 GEMM + residual(x1) -> fp32 d_out (K=768)
    gemm_bf16<3><<<dim3(DIM / BN, MT), 256, GEMM_SMEM>>>(
        hbuf, wfc2, b_fc2, out, nullptr, nullptr, x1, TOKENS, DIM, HIDDEN);
}